// round 14
// baseline (speedup 1.0000x reference)
#include <cuda_runtime.h>
#include <cuda_fp16.h>
#include <math.h>
#include <stdint.h>

#define SEQ    2048
#define HDIM   2048
#define NH     16
#define DN     128
#define DR     64
#define DV     128
#define QL     1536
#define KL     512
#define DFULL  192
#define FUSED_NPAD 2176
#define FUSED_REAL 2112
#define QB_N   3072
#define KVB_N  4096

// ---------------- device scratch (zero-initialized) ----------------
__device__ float g_fused[SEQ * FUSED_NPAD];
__device__ __half g_qp[SEQ * QB_N];
__device__ __half g_kvp[SEQ * KVB_N];
__device__ __half g_H2   [SEQ * HDIM];
__device__ __half g_QN2  [SEQ * QL];
__device__ __half g_KVN2 [SEQ * KL];
__device__ __half g_ATTN2[SEQ * HDIM];
__device__ __half g_WKVA2[FUSED_NPAD * HDIM];   // rows >= 2112 stay 0
__device__ __half g_WQB2 [QB_N * QL];
__device__ __half g_WKVB2[KVB_N * KL];
__device__ __half g_WO2  [HDIM * HDIM];
__device__ __half g_Q2 [NH * SEQ * DFULL];
__device__ __half g_K2 [NH * SEQ * DFULL];
__device__ __half g_V2 [NH * DV * SEQ];         // [h][d][s]

// ---------------- helpers ----------------
__device__ __forceinline__ uint32_t smem_u32(const void* p) {
    uint32_t a;
    asm("{ .reg .u64 t; cvta.to.shared.u64 t, %1; cvt.u32.u64 %0, t; }" : "=r"(a) : "l"(p));
    return a;
}
__device__ __forceinline__ void cp16(uint32_t dst, const void* src) {
    asm volatile("cp.async.cg.shared.global [%0], [%1], 16;" :: "r"(dst), "l"(src));
}
__device__ __forceinline__ void ldsm_x4(uint32_t* r, uint32_t a) {
    asm volatile("ldmatrix.sync.aligned.m8n8.x4.shared.b16 {%0,%1,%2,%3}, [%4];"
                 : "=r"(r[0]), "=r"(r[1]), "=r"(r[2]), "=r"(r[3]) : "r"(a));
}
__device__ __forceinline__ void mma16816(float* c, const uint32_t* a, uint32_t b0, uint32_t b1) {
    asm volatile(
        "mma.sync.aligned.m16n8k16.row.col.f32.f16.f16.f32 "
        "{%0,%1,%2,%3}, {%4,%5,%6,%7}, {%8,%9}, {%0,%1,%2,%3};"
        : "+f"(c[0]), "+f"(c[1]), "+f"(c[2]), "+f"(c[3])
        : "r"(a[0]), "r"(a[1]), "r"(a[2]), "r"(a[3]), "r"(b0), "r"(b1));
}

// ============================================================================
// fp16 GEMM: C = A B^T, K-major fp16 operands; fp32 or fp16 C (outHalf).
// ============================================================================
#define GSMEM (3 * 32768)

__global__ __launch_bounds__(256) void gemm_fp16(
    const __half* __restrict__ A,
    const __half* __restrict__ B,
    float* __restrict__ C,
    int lda, int ldb, int ldc, int K, int outHalf)
{
    const int n0 = blockIdx.x * 128;
    const int m0 = blockIdx.y * 128;
    const int ntiles = K >> 6;

    extern __shared__ char smraw[];
    const uint32_t s0 = smem_u32(smraw);

    const int tid = threadIdx.x;
    const int lane = tid & 31;
    const int wid = tid >> 5;
    const int wm = (wid & 1) * 64;
    const int wn = (wid >> 1) * 32;
    const int g = lane >> 2, t4 = lane & 3;

    const int ra = lane & 15;
    const int sega = (lane >> 4) & 1;
    const int rb = (lane >> 4) * 8 + (lane & 7);
    const int segb = (lane >> 3) & 1;
    uint32_t a_off[4], b_off[2];
#pragma unroll
    for (int mt = 0; mt < 4; mt++) a_off[mt] = (uint32_t)((wm + mt * 16 + ra) * 128);
#pragma unroll
    for (int p = 0; p < 2; p++) b_off[p] = (uint32_t)((wn + p * 16 + rb) * 128);
    const int a_swrow = ra & 7;
    const int b_swrow = rb & 7;

    float c[4][4][4];
#pragma unroll
    for (int i = 0; i < 4; i++)
#pragma unroll
        for (int j = 0; j < 4; j++)
#pragma unroll
            for (int e = 0; e < 4; e++) c[i][j][e] = 0.f;

    auto load_tile = [&](int i, int buf) {
        const __half* Ag = A + (size_t)m0 * lda + (i << 6);
        const __half* Bg = B + (size_t)n0 * ldb + (i << 6);
        const uint32_t da = s0 + buf * 32768;
        const uint32_t db = da + 16384;
#pragma unroll
        for (int t = 0; t < 4; t++) {
            int ch = tid + t * 256;
            int r = ch >> 3;
            int s = ch & 7;
            uint32_t sw = (uint32_t)(r * 128 + ((s ^ (r & 7)) << 4));
            cp16(da + sw, Ag + (size_t)r * lda + s * 8);
            cp16(db + sw, Bg + (size_t)r * ldb + s * 8);
        }
        asm volatile("cp.async.commit_group;");
    };

    load_tile(0, 0);
    if (ntiles > 1) load_tile(1, 1); else asm volatile("cp.async.commit_group;");

    for (int i = 0; i < ntiles; i++) {
        asm volatile("cp.async.wait_group 1;");
        __syncthreads();
        if (i + 2 < ntiles) load_tile(i + 2, (i + 2) % 3);
        else asm volatile("cp.async.commit_group;");

        const uint32_t ab = s0 + (i % 3) * 32768;
        const uint32_t bb = ab + 16384;
#pragma unroll
        for (int kc = 0; kc < 4; kc++) {
            const uint32_t ax = (uint32_t)(((kc * 2 + sega) ^ a_swrow) << 4);
            const uint32_t bx = (uint32_t)(((kc * 2 + segb) ^ b_swrow) << 4);
            uint32_t a[4][4], b[2][4];
#pragma unroll
            for (int mt = 0; mt < 4; mt++) ldsm_x4(a[mt], ab + a_off[mt] + ax);
#pragma unroll
            for (int p = 0; p < 2; p++) ldsm_x4(b[p], bb + b_off[p] + bx);
#pragma unroll
            for (int mt = 0; mt < 4; mt++) {
                mma16816(c[mt][0], a[mt], b[0][0], b[0][1]);
                mma16816(c[mt][1], a[mt], b[0][2], b[0][3]);
                mma16816(c[mt][2], a[mt], b[1][0], b[1][1]);
                mma16816(c[mt][3], a[mt], b[1][2], b[1][3]);
            }
        }
    }

    if (outHalf) {
        __half* Ch = (__half*)C;
#pragma unroll
        for (int mt = 0; mt < 4; mt++)
#pragma unroll
            for (int nt = 0; nt < 4; nt++) {
                int row = m0 + wm + mt * 16 + g;
                int col = n0 + wn + nt * 8 + t4 * 2;
                __half2 lo = __floats2half2_rn(c[mt][nt][0], c[mt][nt][1]);
                __half2 hi = __floats2half2_rn(c[mt][nt][2], c[mt][nt][3]);
                *(__half2*)&Ch[(size_t)row * ldc + col] = lo;
                *(__half2*)&Ch[(size_t)(row + 8) * ldc + col] = hi;
            }
    } else {
#pragma unroll
        for (int mt = 0; mt < 4; mt++)
#pragma unroll
            for (int nt = 0; nt < 4; nt++) {
                int row = m0 + wm + mt * 16 + g;
                int col = n0 + wn + nt * 8 + t4 * 2;
                *(float2*)&C[(size_t)row * ldc + col] = make_float2(c[mt][nt][0], c[mt][nt][1]);
                *(float2*)&C[(size_t)(row + 8) * ldc + col] = make_float2(c[mt][nt][2], c[mt][nt][3]);
            }
    }
}

// ============================================================================
// Fused flash attention (causal) — qb_base allows split launches.
// ============================================================================
#define FSMEM (49152 + 2 * 24576 + 2 * 16384)   // 131072

__global__ __launch_bounds__(256) void flash_mma(
    const __half* __restrict__ Qg_, const __half* __restrict__ Kg_,
    const __half* __restrict__ Vg_, __half* __restrict__ O, int qb_base)
{
    const int qb = qb_base + (int)(gridDim.x - 1) - (int)blockIdx.x;  // big first
    const int h = blockIdx.y;
    const int kend = 2 * qb + 2;

    extern __shared__ char sm[];
    const uint32_t sQ = smem_u32(sm);
    const uint32_t sK = sQ + 49152;
    const uint32_t sV = sK + 2 * 24576;

    const int tid = threadIdx.x, lane = tid & 31, w = tid >> 5;
    const int g = lane >> 2, t4 = lane & 3;

    const __half* Qg = Qg_ + ((size_t)h * SEQ + (size_t)qb * 128) * DFULL;
    const __half* Kg = Kg_ + (size_t)h * SEQ * DFULL;
    const __half* Vg = Vg_ + (size_t)h * DV * SEQ;

    {
#pragma unroll
        for (int t = 0; t < 12; t++) {
            int ch = tid + t * 256;
            int r = ch / 24, s = ch % 24;
            uint32_t sw = (uint32_t)(r * 384 + ((s ^ (r & 7)) << 4));
            cp16(sQ + sw, Qg + r * DFULL + s * 8);
        }
        asm volatile("cp.async.commit_group;");
    }
    auto load_kv = [&](int kb, int buf) {
        const __half* Kt = Kg + (size_t)kb * 64 * DFULL;
#pragma unroll
        for (int t = 0; t < 6; t++) {
            int ch = tid + t * 256;
            int r = ch / 24, s = ch % 24;
            uint32_t sw = (uint32_t)(r * 384 + ((s ^ (r & 7)) << 4));
            cp16(sK + buf * 24576 + sw, Kt + r * DFULL + s * 8);
        }
        const __half* Vt = Vg + kb * 64;
#pragma unroll
        for (int t = 0; t < 4; t++) {
            int ch = tid + t * 256;
            int r = ch >> 3, s = ch & 7;
            uint32_t sw = (uint32_t)(r * 128 + ((s ^ (r & 7)) << 4));
            cp16(sV + buf * 16384 + sw, Vt + (size_t)r * SEQ + s * 8);
        }
        asm volatile("cp.async.commit_group;");
    };
    load_kv(0, 0);
    load_kv(1, 1);
    asm volatile("cp.async.wait_group 1;");
    __syncthreads();

    const int ra = lane & 15, sega = (lane >> 4) & 1;
    const uint32_t q_off = (uint32_t)((w * 16 + ra) * 384);
    const int a_swrow = ra & 7;
    const int rb = ((lane >> 4) << 3) + (lane & 7), segb = (lane >> 3) & 1;
    const int b_swrow = rb & 7;

    float m0 = -INFINITY, m1 = -INFINITY, l0 = 0.f, l1 = 0.f;
    float o[16][4];
#pragma unroll
    for (int i = 0; i < 16; i++)
#pragma unroll
        for (int e = 0; e < 4; e++) o[i][e] = 0.f;

    for (int kb = 0; kb < kend; kb++) {
        const uint32_t kbuf = sK + (kb & 1) * 24576;
        const uint32_t vbuf = sV + (kb & 1) * 16384;

        float S[8][4];
#pragma unroll
        for (int j = 0; j < 8; j++)
#pragma unroll
            for (int e = 0; e < 4; e++) S[j][e] = 0.f;

#pragma unroll
        for (int ks = 0; ks < 12; ks++) {
            uint32_t a[4];
            ldsm_x4(a, sQ + q_off + (uint32_t)(((ks * 2 + sega) ^ a_swrow) << 4));
            const uint32_t bx = (uint32_t)(((ks * 2 + segb) ^ b_swrow) << 4);
#pragma unroll
            for (int nt = 0; nt < 4; nt++) {
                uint32_t b[4];
                ldsm_x4(b, kbuf + (uint32_t)((nt * 16 + rb) * 384) + bx);
                mma16816(S[nt * 2],     a, b[0], b[1]);
                mma16816(S[nt * 2 + 1], a, b[2], b[3]);
            }
        }

        if (kb >= 2 * qb) {
            const int row0 = qb * 128 + w * 16 + g;
            const int colb = kb * 64 + t4 * 2;
#pragma unroll
            for (int j = 0; j < 8; j++) {
#pragma unroll
                for (int e = 0; e < 2; e++) {
                    int col = colb + j * 8 + e;
                    if (col > row0) S[j][e] = -INFINITY;
                    if (col > row0 + 8) S[j][2 + e] = -INFINITY;
                }
            }
        }

        float mx0 = -INFINITY, mx1 = -INFINITY;
#pragma unroll
        for (int j = 0; j < 8; j++) {
            mx0 = fmaxf(mx0, fmaxf(S[j][0], S[j][1]));
            mx1 = fmaxf(mx1, fmaxf(S[j][2], S[j][3]));
        }
        mx0 = fmaxf(mx0, __shfl_xor_sync(0xffffffffu, mx0, 1));
        mx0 = fmaxf(mx0, __shfl_xor_sync(0xffffffffu, mx0, 2));
        mx1 = fmaxf(mx1, __shfl_xor_sync(0xffffffffu, mx1, 1));
        mx1 = fmaxf(mx1, __shfl_xor_sync(0xffffffffu, mx1, 2));
        const float mn0 = fmaxf(m0, mx0), mn1 = fmaxf(m1, mx1);
        const float c0 = __expf(m0 - mn0), c1 = __expf(m1 - mn1);
        float s0 = 0.f, s1 = 0.f;
#pragma unroll
        for (int j = 0; j < 8; j++) {
            S[j][0] = __expf(S[j][0] - mn0);
            S[j][1] = __expf(S[j][1] - mn0);
            S[j][2] = __expf(S[j][2] - mn1);
            S[j][3] = __expf(S[j][3] - mn1);
            s0 += S[j][0] + S[j][1];
            s1 += S[j][2] + S[j][3];
        }
        s0 += __shfl_xor_sync(0xffffffffu, s0, 1);
        s0 += __shfl_xor_sync(0xffffffffu, s0, 2);
        s1 += __shfl_xor_sync(0xffffffffu, s1, 1);
        s1 += __shfl_xor_sync(0xffffffffu, s1, 2);
        l0 = l0 * c0 + s0;
        l1 = l1 * c1 + s1;
        m0 = mn0; m1 = mn1;
#pragma unroll
        for (int i = 0; i < 16; i++) {
            o[i][0] *= c0; o[i][1] *= c0;
            o[i][2] *= c1; o[i][3] *= c1;
        }

        uint32_t ap[4][4];
#pragma unroll
        for (int i = 0; i < 4; i++) {
            __half2 h0 = __floats2half2_rn(S[2 * i][0], S[2 * i][1]);
            __half2 h1 = __floats2half2_rn(S[2 * i][2], S[2 * i][3]);
            __half2 h2 = __floats2half2_rn(S[2 * i + 1][0], S[2 * i + 1][1]);
            __half2 h3 = __floats2half2_rn(S[2 * i + 1][2], S[2 * i + 1][3]);
            ap[i][0] = *(uint32_t*)&h0;
            ap[i][1] = *(uint32_t*)&h1;
            ap[i][2] = *(uint32_t*)&h2;
            ap[i][3] = *(uint32_t*)&h3;
        }

#pragma unroll
        for (int i = 0; i < 4; i++) {
            const uint32_t vx = (uint32_t)(((i * 2 + segb) ^ b_swrow) << 4);
#pragma unroll
            for (int nt = 0; nt < 8; nt++) {
                uint32_t b[4];
                ldsm_x4(b, vbuf + (uint32_t)((nt * 16 + rb) * 128) + vx);
                mma16816(o[nt * 2],     ap[i], b[0], b[1]);
                mma16816(o[nt * 2 + 1], ap[i], b[2], b[3]);
            }
        }

        __syncthreads();
        if (kb + 2 < kend) load_kv(kb + 2, kb & 1);
        else asm volatile("cp.async.commit_group;");
        asm volatile("cp.async.wait_group 1;");
        __syncthreads();
    }

    const float inv0 = 1.f / l0, inv1 = 1.f / l1;
    const int r0 = qb * 128 + w * 16 + g;
#pragma unroll
    for (int nt = 0; nt < 16; nt++) {
        const int col = h * DV + nt * 8 + t4 * 2;
        __half2 lo = __floats2half2_rn(o[nt][0] * inv0, o[nt][1] * inv0);
        __half2 hi = __floats2half2_rn(o[nt][2] * inv1, o[nt][3] * inv1);
        *(__half2*)&O[(size_t)r0 * HDIM + col] = lo;
        *(__half2*)&O[(size_t)(r0 + 8) * HDIM + col] = hi;
    }
}

// ---------------- fp32 -> fp16 convert (8/thread) ----------------
__global__ __launch_bounds__(256) void cvt_act8(
    const float4* __restrict__ X, uint2* __restrict__ X2, int total4)
{
    int i = blockIdx.x * 512 + threadIdx.x;
#pragma unroll
    for (int t = 0; t < 2; t++, i += 256) {
        if (i < total4) {
            float4 v = X[i];
            __half2 a = __floats2half2_rn(v.x, v.y);
            __half2 b = __floats2half2_rn(v.z, v.w);
            uint2 o;
            o.x = *(uint32_t*)&a;
            o.y = *(uint32_t*)&b;
            X2[i] = o;
        }
    }
}

// ---------------- weight transpose+convert (vectorized): W[K,N] -> Wt[N,K] fp16 ----------------
__global__ __launch_bounds__(256) void transpose_w_h(
    const float* __restrict__ W, __half* __restrict__ Wt, int K, int N)
{
    __shared__ __half tt[32][40];
    const int kb = blockIdx.x * 32, nb = blockIdx.y * 32;
    const int tx = threadIdx.x & 7, ty = threadIdx.x >> 3;
    float4 v = *(const float4*)&W[(size_t)(kb + ty) * N + nb + tx * 4];
    tt[tx * 4 + 0][ty] = __float2half_rn(v.x);
    tt[tx * 4 + 1][ty] = __float2half_rn(v.y);
    tt[tx * 4 + 2][ty] = __float2half_rn(v.z);
    tt[tx * 4 + 3][ty] = __float2half_rn(v.w);
    __syncthreads();
    uint2 o;
    __half2 a, b;
    a.x = tt[ty][tx * 4 + 0]; a.y = tt[ty][tx * 4 + 1];
    b.x = tt[ty][tx * 4 + 2]; b.y = tt[ty][tx * 4 + 3];
    o.x = *(uint32_t*)&a;
    o.y = *(uint32_t*)&b;
    *(uint2*)&Wt[(size_t)(nb + ty) * K + kb + tx * 4] = o;
}

// ---------------- RMSNorm -> fp16 (float4 loads, 4-half stores) ----------------
__global__ __launch_bounds__(256) void rmsnorm_h(
    const float* __restrict__ src, const float* __restrict__ gamma,
    __half* __restrict__ dst, int stride, int len)
{
    const int row = blockIdx.x;
    const float* x = src + (size_t)row * stride;
    const int len4 = len >> 2;
    float ss = 0.f;
    for (int i = threadIdx.x; i < len4; i += 256) {
        float4 v = ((const float4*)x)[i];
        ss += v.x * v.x + v.y * v.y + v.z * v.z + v.w * v.w;
    }
#pragma unroll
    for (int o = 16; o; o >>= 1) ss += __shfl_xor_sync(0xffffffffu, ss, o);
    __shared__ float ws[8]; __shared__ float s_inv;
    if ((threadIdx.x & 31) == 0) ws[threadIdx.x >> 5] = ss;
    __syncthreads();
    if (threadIdx.x == 0) {
        float t = 0.f;
#pragma unroll
        for (int i = 0; i < 8; i++) t += ws[i];
        s_inv = rsqrtf(t / (float)len + 1e-6f);
    }
    __syncthreads();
    const float inv = s_inv;
    __half* out = dst + (size_t)row * len;
    for (int i = threadIdx.x; i < len4; i += 256) {
        float4 v = ((const float4*)x)[i];
        float4 gm = ((const float4*)gamma)[i];
        __half2 a = __floats2half2_rn(v.x * gm.x * inv, v.y * gm.y * inv);
        __half2 b = __floats2half2_rn(v.z * gm.z * inv, v.w * gm.w * inv);
        uint2 o;
        o.x = *(uint32_t*)&a;
        o.y = *(uint32_t*)&b;
        *(uint2*)&out[i * 4] = o;
    }
}

// ---------------- RoPE + pack -> fp16 ----------------
__global__ __launch_bounds__(192) void rope_pack_h(
    const __half* __restrict__ qp, const __half* __restrict__ kvp,
    const float* __restrict__ fused,
    __half* __restrict__ Q2, __half* __restrict__ K2,
    __half* __restrict__ V2)
{
    const int s = blockIdx.x, h = blockIdx.y, d = threadIdx.x;
    const float scale = 0.07216878364870323f; // 1/sqrt(192)
    float qv, kv;
    if (d < DN) {
        qv = __half2float(qp[(size_t)s * QB_N + h * DFULL + d]) * scale;
        kv = __half2float(kvp[(size_t)s * KVB_N + h * (DN + DV) + d]);
        V2[((size_t)h * DV + d) * SEQ + s] = kvp[(size_t)s * KVB_N + h * (DN + DV) + DN + d];
    } else {
        int j = d - DN, i = j & 31;
        float inv_freq = powf(10000.f, -(float)(2 * i) / 64.f);
        float sn, cs;
        sincosf((float)s * inv_freq, &sn, &cs);
        size_t qoff = (size_t)s * QB_N + h * DFULL + DN;
        float qpe = __half2float(qp[qoff + j]);
        float qrot = (j < 32) ? -__half2float(qp[qoff + j + 32])
                              :  __half2float(qp[qoff + j - 32]);
        size_t koff = (size_t)s * FUSED_NPAD + (QL + KL);
        float kpe = fused[koff + j];
        float krot = (j < 32) ? -fused[koff + j + 32] : fused[koff + j - 32];
        qv = (qpe * cs + qrot * sn) * scale;
        kv = kpe * cs + krot * sn;
    }
    Q2[((size_t)h * SEQ + s) * DFULL + d] = __float2half_rn(qv);
    K2[((size_t)h * SEQ + s) * DFULL + d] = __float2half_rn(kv);
}

// ---------------- launcher (multi-stream fork/join, capture-legal) ----------------
extern "C" void kernel_launch(void* const* d_in, const int* in_sizes, int n_in,
                              void* d_out, int out_size)
{
    const float* hidden     = (const float*)d_in[0];
    const float* w_kv_a     = (const float*)d_in[1];
    const float* q_a_gamma  = (const float*)d_in[2];
    const float* w_qb       = (const float*)d_in[3];
    const float* kv_a_gamma = (const float*)d_in[4];
    const float* w_kvb      = (const float*)d_in[5];
    const float* w_o        = (const float*)d_in[6];
    float* out = (float*)d_out;

    static float* fused = nullptr;
    static __half *qp, *kvp, *H2, *QN2, *KVN2, *ATTN2, *WKVA2, *WQB2, *WKVB2, *WO2, *Q2, *K2, *V2;
    static cudaStream_t sB, sC;
    static cudaEvent_t evRoot, evB, evG1, evC, evFA, evG4a;
    if (!fused) {
        cudaGetSymbolAddress((void**)&fused, g_fused);
        cudaGetSymbolAddress((void**)&qp,    g_qp);
        cudaGetSymbolAddress((void**)&kvp,   g_kvp);
        cudaGetSymbolAddress((void**)&H2,    g_H2);
        cudaGetSymbolAddress((void**)&QN2,   g_QN2);
        cudaGetSymbolAddress((void**)&KVN2,  g_KVN2);
        cudaGetSymbolAddress((void**)&ATTN2, g_ATTN2);
        cudaGetSymbolAddress((void**)&WKVA2, g_WKVA2);
        cudaGetSymbolAddress((void**)&WQB2,  g_WQB2);
        cudaGetSymbolAddress((void**)&WKVB2, g_WKVB2);
        cudaGetSymbolAddress((void**)&WO2,   g_WO2);
        cudaGetSymbolAddress((void**)&Q2,    g_Q2);
        cudaGetSymbolAddress((void**)&K2,    g_K2);
        cudaGetSymbolAddress((void**)&V2,    g_V2);
        cudaFuncSetAttribute(gemm_fp16, cudaFuncAttributeMaxDynamicSharedMemorySize, GSMEM);
        cudaFuncSetAttribute(flash_mma, cudaFuncAttributeMaxDynamicSharedMemorySize, FSMEM);
        cudaStreamCreateWithFlags(&sB, cudaStreamNonBlocking);
        cudaStreamCreateWithFlags(&sC, cudaStreamNonBlocking);
        cudaEventCreateWithFlags(&evRoot, cudaEventDisableTiming);
        cudaEventCreateWithFlags(&evB,    cudaEventDisableTiming);
        cudaEventCreateWithFlags(&evG1,   cudaEventDisableTiming);
        cudaEventCreateWithFlags(&evC,    cudaEventDisableTiming);
        cudaEventCreateWithFlags(&evFA,   cudaEventDisableTiming);
        cudaEventCreateWithFlags(&evG4a,  cudaEventDisableTiming);
    }

    // ---- fork: stream B does the GEMM1-independent weight transposes ----
    cudaEventRecord(evRoot, 0);
    cudaStreamWaitEvent(sB, evRoot, 0);
    transpose_w_h<<<dim3(QL / 32, QB_N / 32), 256, 0, sB>>>(w_qb, WQB2, QL, QB_N);
    transpose_w_h<<<dim3(KL / 32, KVB_N / 32), 256, 0, sB>>>(w_kvb, WKVB2, KL, KVB_N);
    transpose_w_h<<<dim3(HDIM / 32, HDIM / 32), 256, 0, sB>>>(w_o, WO2, HDIM, HDIM);
    cudaEventRecord(evB, sB);

    // ---- main stream: GEMM1 critical path ----
    cvt_act8<<<(SEQ * HDIM / 4 + 511) / 512, 256>>>(
        (const float4*)hidden, (uint2*)H2, SEQ * HDIM / 4);
    transpose_w_h<<<dim3(HDIM / 32, FUSED_REAL / 32), 256>>>(w_kv_a, WKVA2, HDIM, FUSED_REAL);
    gemm_fp16<<<dim3(FUSED_NPAD / 128, SEQ / 128), 256, GSMEM>>>(
        H2, WKVA2, fused, HDIM, HDIM, FUSED_NPAD, HDIM, 0);
    cudaEventRecord(evG1, 0);

    // ---- stream C: KV branch (rmsnorm_kv -> GEMM3, fp16 out) ----
    cudaStreamWaitEvent(sC, evG1, 0);
    cudaStreamWaitEvent(sC, evB, 0);
    rmsnorm_h<<<SEQ, 256, 0, sC>>>(fused + QL, kv_a_gamma, KVN2, FUSED_NPAD, KL);
    gemm_fp16<<<dim3(KVB_N / 128, SEQ / 128), 256, GSMEM, sC>>>(
        KVN2, WKVB2, (float*)kvp, KL, KL, KVB_N, KL, 1);
    cudaEventRecord(evC, sC);

    // ---- main stream: Q branch (fp16 out) ----
    rmsnorm_h<<<SEQ, 256>>>(fused, q_a_gamma, QN2, FUSED_NPAD, QL);
    cudaStreamWaitEvent(0, evB, 0);
    gemm_fp16<<<dim3(QB_N / 128, SEQ / 128), 256, GSMEM>>>(
        QN2, WQB2, (float*)qp, QL, QL, QB_N, QL, 1);

    // ---- join: rope needs qp (main) + kvp (stream C) ----
    cudaStreamWaitEvent(0, evC, 0);
    rope_pack_h<<<dim3(SEQ, NH), 192>>>(qp, kvp, fused, Q2, K2, V2);

    // ---- flash split: big half first, then overlap GEMM4a with small half ----
    flash_mma<<<dim3(8, NH), 256, FSMEM>>>(Q2, K2, V2, ATTN2, 8);   // qb 8..15
    cudaEventRecord(evFA, 0);

    // stream C: GEMM4a on rows 1024..2047 (ready after flashA; WO2 via earlier evB wait)
    cudaStreamWaitEvent(sC, evFA, 0);
    gemm_fp16<<<dim3(HDIM / 128, 8), 256, GSMEM, sC>>>(
        ATTN2 + (size_t)1024 * HDIM, WO2, out + (size_t)1024 * HDIM,
        HDIM, HDIM, HDIM, HDIM, 0);
    cudaEventRecord(evG4a, sC);

    // main: flashB (qb 0..7), then GEMM4b on rows 0..1023
    flash_mma<<<dim3(8, NH), 256, FSMEM>>>(Q2, K2, V2, ATTN2, 0);
    gemm_fp16<<<dim3(HDIM / 128, 8), 256, GSMEM>>>(
        ATTN2, WO2, out, HDIM, HDIM, HDIM, HDIM, 0);
    cudaStreamWaitEvent(0, evG4a, 0);   // join for graph completeness
}

// round 15
// speedup vs baseline: 1.0731x; 1.0731x over previous
#include <cuda_runtime.h>
#include <cuda_fp16.h>
#include <math.h>
#include <stdint.h>

#define SEQ    2048
#define HDIM   2048
#define NH     16
#define DN     128
#define DR     64
#define DV     128
#define QL     1536
#define KL     512
#define DFULL  192
#define FUSED_NPAD 2176
#define FUSED_REAL 2112
#define QB_N   3072
#define KVB_N  4096

// ---------------- device scratch (zero-initialized) ----------------
__device__ float g_fused[SEQ * FUSED_NPAD];
__device__ __half g_qp[SEQ * QB_N];
__device__ __half g_kvp[SEQ * KVB_N];
__device__ __half g_H2   [SEQ * HDIM];
__device__ __half g_QN2  [SEQ * QL];
__device__ __half g_KVN2 [SEQ * KL];
__device__ __half g_ATTN2[SEQ * HDIM];
__device__ __half g_WKVA2[FUSED_NPAD * HDIM];   // rows >= 2112 stay 0
__device__ __half g_WQB2 [QB_N * QL];
__device__ __half g_WKVB2[KVB_N * KL];
__device__ __half g_WO2  [HDIM * HDIM];
__device__ __half g_Q2 [NH * SEQ * DFULL];
__device__ __half g_K2 [NH * SEQ * DFULL];
__device__ __half g_V2 [NH * DV * SEQ];         // [h][d][s]

// ---------------- helpers ----------------
__device__ __forceinline__ uint32_t smem_u32(const void* p) {
    uint32_t a;
    asm("{ .reg .u64 t; cvta.to.shared.u64 t, %1; cvt.u32.u64 %0, t; }" : "=r"(a) : "l"(p));
    return a;
}
__device__ __forceinline__ void cp16(uint32_t dst, const void* src) {
    asm volatile("cp.async.cg.shared.global [%0], [%1], 16;" :: "r"(dst), "l"(src));
}
__device__ __forceinline__ void ldsm_x4(uint32_t* r, uint32_t a) {
    asm volatile("ldmatrix.sync.aligned.m8n8.x4.shared.b16 {%0,%1,%2,%3}, [%4];"
                 : "=r"(r[0]), "=r"(r[1]), "=r"(r[2]), "=r"(r[3]) : "r"(a));
}
__device__ __forceinline__ void mma16816(float* c, const uint32_t* a, uint32_t b0, uint32_t b1) {
    asm volatile(
        "mma.sync.aligned.m16n8k16.row.col.f32.f16.f16.f32 "
        "{%0,%1,%2,%3}, {%4,%5,%6,%7}, {%8,%9}, {%0,%1,%2,%3};"
        : "+f"(c[0]), "+f"(c[1]), "+f"(c[2]), "+f"(c[3])
        : "r"(a[0]), "r"(a[1]), "r"(a[2]), "r"(a[3]), "r"(b0), "r"(b1));
}

// ============================================================================
// fp16 GEMM: C = A B^T, K-major fp16 operands; fp32 or fp16 C (outHalf).
// ============================================================================
#define GSMEM (3 * 32768)

__global__ __launch_bounds__(256) void gemm_fp16(
    const __half* __restrict__ A,
    const __half* __restrict__ B,
    float* __restrict__ C,
    int lda, int ldb, int ldc, int K, int outHalf)
{
    const int n0 = blockIdx.x * 128;
    const int m0 = blockIdx.y * 128;
    const int ntiles = K >> 6;

    extern __shared__ char smraw[];
    const uint32_t s0 = smem_u32(smraw);

    const int tid = threadIdx.x;
    const int lane = tid & 31;
    const int wid = tid >> 5;
    const int wm = (wid & 1) * 64;
    const int wn = (wid >> 1) * 32;
    const int g = lane >> 2, t4 = lane & 3;

    const int ra = lane & 15;
    const int sega = (lane >> 4) & 1;
    const int rb = (lane >> 4) * 8 + (lane & 7);
    const int segb = (lane >> 3) & 1;
    uint32_t a_off[4], b_off[2];
#pragma unroll
    for (int mt = 0; mt < 4; mt++) a_off[mt] = (uint32_t)((wm + mt * 16 + ra) * 128);
#pragma unroll
    for (int p = 0; p < 2; p++) b_off[p] = (uint32_t)((wn + p * 16 + rb) * 128);
    const int a_swrow = ra & 7;
    const int b_swrow = rb & 7;

    float c[4][4][4];
#pragma unroll
    for (int i = 0; i < 4; i++)
#pragma unroll
        for (int j = 0; j < 4; j++)
#pragma unroll
            for (int e = 0; e < 4; e++) c[i][j][e] = 0.f;

    auto load_tile = [&](int i, int buf) {
        const __half* Ag = A + (size_t)m0 * lda + (i << 6);
        const __half* Bg = B + (size_t)n0 * ldb + (i << 6);
        const uint32_t da = s0 + buf * 32768;
        const uint32_t db = da + 16384;
#pragma unroll
        for (int t = 0; t < 4; t++) {
            int ch = tid + t * 256;
            int r = ch >> 3;
            int s = ch & 7;
            uint32_t sw = (uint32_t)(r * 128 + ((s ^ (r & 7)) << 4));
            cp16(da + sw, Ag + (size_t)r * lda + s * 8);
            cp16(db + sw, Bg + (size_t)r * ldb + s * 8);
        }
        asm volatile("cp.async.commit_group;");
    };

    load_tile(0, 0);
    if (ntiles > 1) load_tile(1, 1); else asm volatile("cp.async.commit_group;");

    for (int i = 0; i < ntiles; i++) {
        asm volatile("cp.async.wait_group 1;");
        __syncthreads();
        if (i + 2 < ntiles) load_tile(i + 2, (i + 2) % 3);
        else asm volatile("cp.async.commit_group;");

        const uint32_t ab = s0 + (i % 3) * 32768;
        const uint32_t bb = ab + 16384;
#pragma unroll
        for (int kc = 0; kc < 4; kc++) {
            const uint32_t ax = (uint32_t)(((kc * 2 + sega) ^ a_swrow) << 4);
            const uint32_t bx = (uint32_t)(((kc * 2 + segb) ^ b_swrow) << 4);
            uint32_t a[4][4], b[2][4];
#pragma unroll
            for (int mt = 0; mt < 4; mt++) ldsm_x4(a[mt], ab + a_off[mt] + ax);
#pragma unroll
            for (int p = 0; p < 2; p++) ldsm_x4(b[p], bb + b_off[p] + bx);
#pragma unroll
            for (int mt = 0; mt < 4; mt++) {
                mma16816(c[mt][0], a[mt], b[0][0], b[0][1]);
                mma16816(c[mt][1], a[mt], b[0][2], b[0][3]);
                mma16816(c[mt][2], a[mt], b[1][0], b[1][1]);
                mma16816(c[mt][3], a[mt], b[1][2], b[1][3]);
            }
        }
    }

    if (outHalf) {
        __half* Ch = (__half*)C;
#pragma unroll
        for (int mt = 0; mt < 4; mt++)
#pragma unroll
            for (int nt = 0; nt < 4; nt++) {
                int row = m0 + wm + mt * 16 + g;
                int col = n0 + wn + nt * 8 + t4 * 2;
                __half2 lo = __floats2half2_rn(c[mt][nt][0], c[mt][nt][1]);
                __half2 hi = __floats2half2_rn(c[mt][nt][2], c[mt][nt][3]);
                *(__half2*)&Ch[(size_t)row * ldc + col] = lo;
                *(__half2*)&Ch[(size_t)(row + 8) * ldc + col] = hi;
            }
    } else {
#pragma unroll
        for (int mt = 0; mt < 4; mt++)
#pragma unroll
            for (int nt = 0; nt < 4; nt++) {
                int row = m0 + wm + mt * 16 + g;
                int col = n0 + wn + nt * 8 + t4 * 2;
                *(float2*)&C[(size_t)row * ldc + col] = make_float2(c[mt][nt][0], c[mt][nt][1]);
                *(float2*)&C[(size_t)(row + 8) * ldc + col] = make_float2(c[mt][nt][2], c[mt][nt][3]);
            }
    }
}

// ============================================================================
// Fused flash attention (causal) — unified grid, big tiles first (R13 config).
// ============================================================================
#define FSMEM (49152 + 2 * 24576 + 2 * 16384)   // 131072

__global__ __launch_bounds__(256) void flash_mma(
    const __half* __restrict__ Qg_, const __half* __restrict__ Kg_,
    const __half* __restrict__ Vg_, __half* __restrict__ O)
{
    const int qb = (int)(gridDim.x - 1) - (int)blockIdx.x;  // big first
    const int h = blockIdx.y;
    const int kend = 2 * qb + 2;

    extern __shared__ char sm[];
    const uint32_t sQ = smem_u32(sm);
    const uint32_t sK = sQ + 49152;
    const uint32_t sV = sK + 2 * 24576;

    const int tid = threadIdx.x, lane = tid & 31, w = tid >> 5;
    const int g = lane >> 2, t4 = lane & 3;

    const __half* Qg = Qg_ + ((size_t)h * SEQ + (size_t)qb * 128) * DFULL;
    const __half* Kg = Kg_ + (size_t)h * SEQ * DFULL;
    const __half* Vg = Vg_ + (size_t)h * DV * SEQ;

    {
#pragma unroll
        for (int t = 0; t < 12; t++) {
            int ch = tid + t * 256;
            int r = ch / 24, s = ch % 24;
            uint32_t sw = (uint32_t)(r * 384 + ((s ^ (r & 7)) << 4));
            cp16(sQ + sw, Qg + r * DFULL + s * 8);
        }
        asm volatile("cp.async.commit_group;");
    }
    auto load_kv = [&](int kb, int buf) {
        const __half* Kt = Kg + (size_t)kb * 64 * DFULL;
#pragma unroll
        for (int t = 0; t < 6; t++) {
            int ch = tid + t * 256;
            int r = ch / 24, s = ch % 24;
            uint32_t sw = (uint32_t)(r * 384 + ((s ^ (r & 7)) << 4));
            cp16(sK + buf * 24576 + sw, Kt + r * DFULL + s * 8);
        }
        const __half* Vt = Vg + kb * 64;
#pragma unroll
        for (int t = 0; t < 4; t++) {
            int ch = tid + t * 256;
            int r = ch >> 3, s = ch & 7;
            uint32_t sw = (uint32_t)(r * 128 + ((s ^ (r & 7)) << 4));
            cp16(sV + buf * 16384 + sw, Vt + (size_t)r * SEQ + s * 8);
        }
        asm volatile("cp.async.commit_group;");
    };
    load_kv(0, 0);
    load_kv(1, 1);
    asm volatile("cp.async.wait_group 1;");
    __syncthreads();

    const int ra = lane & 15, sega = (lane >> 4) & 1;
    const uint32_t q_off = (uint32_t)((w * 16 + ra) * 384);
    const int a_swrow = ra & 7;
    const int rb = ((lane >> 4) << 3) + (lane & 7), segb = (lane >> 3) & 1;
    const int b_swrow = rb & 7;

    float m0 = -INFINITY, m1 = -INFINITY, l0 = 0.f, l1 = 0.f;
    float o[16][4];
#pragma unroll
    for (int i = 0; i < 16; i++)
#pragma unroll
        for (int e = 0; e < 4; e++) o[i][e] = 0.f;

    for (int kb = 0; kb < kend; kb++) {
        const uint32_t kbuf = sK + (kb & 1) * 24576;
        const uint32_t vbuf = sV + (kb & 1) * 16384;

        float S[8][4];
#pragma unroll
        for (int j = 0; j < 8; j++)
#pragma unroll
            for (int e = 0; e < 4; e++) S[j][e] = 0.f;

#pragma unroll
        for (int ks = 0; ks < 12; ks++) {
            uint32_t a[4];
            ldsm_x4(a, sQ + q_off + (uint32_t)(((ks * 2 + sega) ^ a_swrow) << 4));
            const uint32_t bx = (uint32_t)(((ks * 2 + segb) ^ b_swrow) << 4);
#pragma unroll
            for (int nt = 0; nt < 4; nt++) {
                uint32_t b[4];
                ldsm_x4(b, kbuf + (uint32_t)((nt * 16 + rb) * 384) + bx);
                mma16816(S[nt * 2],     a, b[0], b[1]);
                mma16816(S[nt * 2 + 1], a, b[2], b[3]);
            }
        }

        if (kb >= 2 * qb) {
            const int row0 = qb * 128 + w * 16 + g;
            const int colb = kb * 64 + t4 * 2;
#pragma unroll
            for (int j = 0; j < 8; j++) {
#pragma unroll
                for (int e = 0; e < 2; e++) {
                    int col = colb + j * 8 + e;
                    if (col > row0) S[j][e] = -INFINITY;
                    if (col > row0 + 8) S[j][2 + e] = -INFINITY;
                }
            }
        }

        float mx0 = -INFINITY, mx1 = -INFINITY;
#pragma unroll
        for (int j = 0; j < 8; j++) {
            mx0 = fmaxf(mx0, fmaxf(S[j][0], S[j][1]));
            mx1 = fmaxf(mx1, fmaxf(S[j][2], S[j][3]));
        }
        mx0 = fmaxf(mx0, __shfl_xor_sync(0xffffffffu, mx0, 1));
        mx0 = fmaxf(mx0, __shfl_xor_sync(0xffffffffu, mx0, 2));
        mx1 = fmaxf(mx1, __shfl_xor_sync(0xffffffffu, mx1, 1));
        mx1 = fmaxf(mx1, __shfl_xor_sync(0xffffffffu, mx1, 2));
        const float mn0 = fmaxf(m0, mx0), mn1 = fmaxf(m1, mx1);
        const float c0 = __expf(m0 - mn0), c1 = __expf(m1 - mn1);
        float s0 = 0.f, s1 = 0.f;
#pragma unroll
        for (int j = 0; j < 8; j++) {
            S[j][0] = __expf(S[j][0] - mn0);
            S[j][1] = __expf(S[j][1] - mn0);
            S[j][2] = __expf(S[j][2] - mn1);
            S[j][3] = __expf(S[j][3] - mn1);
            s0 += S[j][0] + S[j][1];
            s1 += S[j][2] + S[j][3];
        }
        s0 += __shfl_xor_sync(0xffffffffu, s0, 1);
        s0 += __shfl_xor_sync(0xffffffffu, s0, 2);
        s1 += __shfl_xor_sync(0xffffffffu, s1, 1);
        s1 += __shfl_xor_sync(0xffffffffu, s1, 2);
        l0 = l0 * c0 + s0;
        l1 = l1 * c1 + s1;
        m0 = mn0; m1 = mn1;
#pragma unroll
        for (int i = 0; i < 16; i++) {
            o[i][0] *= c0; o[i][1] *= c0;
            o[i][2] *= c1; o[i][3] *= c1;
        }

        uint32_t ap[4][4];
#pragma unroll
        for (int i = 0; i < 4; i++) {
            __half2 h0 = __floats2half2_rn(S[2 * i][0], S[2 * i][1]);
            __half2 h1 = __floats2half2_rn(S[2 * i][2], S[2 * i][3]);
            __half2 h2 = __floats2half2_rn(S[2 * i + 1][0], S[2 * i + 1][1]);
            __half2 h3 = __floats2half2_rn(S[2 * i + 1][2], S[2 * i + 1][3]);
            ap[i][0] = *(uint32_t*)&h0;
            ap[i][1] = *(uint32_t*)&h1;
            ap[i][2] = *(uint32_t*)&h2;
            ap[i][3] = *(uint32_t*)&h3;
        }

#pragma unroll
        for (int i = 0; i < 4; i++) {
            const uint32_t vx = (uint32_t)(((i * 2 + segb) ^ b_swrow) << 4);
#pragma unroll
            for (int nt = 0; nt < 8; nt++) {
                uint32_t b[4];
                ldsm_x4(b, vbuf + (uint32_t)((nt * 16 + rb) * 128) + vx);
                mma16816(o[nt * 2],     ap[i], b[0], b[1]);
                mma16816(o[nt * 2 + 1], ap[i], b[2], b[3]);
            }
        }

        __syncthreads();
        if (kb + 2 < kend) load_kv(kb + 2, kb & 1);
        else asm volatile("cp.async.commit_group;");
        asm volatile("cp.async.wait_group 1;");
        __syncthreads();
    }

    const float inv0 = 1.f / l0, inv1 = 1.f / l1;
    const int r0 = qb * 128 + w * 16 + g;
#pragma unroll
    for (int nt = 0; nt < 16; nt++) {
        const int col = h * DV + nt * 8 + t4 * 2;
        __half2 lo = __floats2half2_rn(o[nt][0] * inv0, o[nt][1] * inv0);
        __half2 hi = __floats2half2_rn(o[nt][2] * inv1, o[nt][3] * inv1);
        *(__half2*)&O[(size_t)r0 * HDIM + col] = lo;
        *(__half2*)&O[(size_t)(r0 + 8) * HDIM + col] = hi;
    }
}

// ---------------- fp32 -> fp16 convert (4/thread) ----------------
__global__ __launch_bounds__(256) void cvt_act4(
    const float4* __restrict__ X, uint2* __restrict__ X2, int total4)
{
    int i = blockIdx.x * 256 + threadIdx.x;
    if (i >= total4) return;
    float4 v = X[i];
    __half2 a = __floats2half2_rn(v.x, v.y);
    __half2 b = __floats2half2_rn(v.z, v.w);
    uint2 o;
    o.x = *(uint32_t*)&a;
    o.y = *(uint32_t*)&b;
    X2[i] = o;
}

// ---------------- weight transpose+convert (vectorized): W[K,N] -> Wt[N,K] fp16 ----------------
__global__ __launch_bounds__(256) void transpose_w_h(
    const float* __restrict__ W, __half* __restrict__ Wt, int K, int N)
{
    __shared__ __half tt[32][40];
    const int kb = blockIdx.x * 32, nb = blockIdx.y * 32;
    const int tx = threadIdx.x & 7, ty = threadIdx.x >> 3;
    float4 v = *(const float4*)&W[(size_t)(kb + ty) * N + nb + tx * 4];
    tt[tx * 4 + 0][ty] = __float2half_rn(v.x);
    tt[tx * 4 + 1][ty] = __float2half_rn(v.y);
    tt[tx * 4 + 2][ty] = __float2half_rn(v.z);
    tt[tx * 4 + 3][ty] = __float2half_rn(v.w);
    __syncthreads();
    uint2 o;
    __half2 a, b;
    a.x = tt[ty][tx * 4 + 0]; a.y = tt[ty][tx * 4 + 1];
    b.x = tt[ty][tx * 4 + 2]; b.y = tt[ty][tx * 4 + 3];
    o.x = *(uint32_t*)&a;
    o.y = *(uint32_t*)&b;
    *(uint2*)&Wt[(size_t)(nb + ty) * K + kb + tx * 4] = o;
}

// ---------------- V pack: kvp[s][h*256+128+d] -> V2[h][d][s], coalesced ----------------
__global__ __launch_bounds__(256) void v_pack(
    const __half* __restrict__ kvp, __half* __restrict__ V2)
{
    __shared__ __half tt[32][40];   // [d][s]
    const int s0 = blockIdx.x * 32;
    const int d0 = blockIdx.y * 32;
    const int h  = blockIdx.z;
    const int tx = threadIdx.x & 7, ty = threadIdx.x >> 3;   // ty 0..31
    // read 32 s-rows x 32 d (uint2 = 4 halves per thread)
    uint2 v = *(const uint2*)&kvp[(size_t)(s0 + ty) * KVB_N + h * (DN + DV) + DN + d0 + tx * 4];
    __half2 a = *(__half2*)&v.x, b = *(__half2*)&v.y;
    tt[tx * 4 + 0][ty] = a.x;
    tt[tx * 4 + 1][ty] = a.y;
    tt[tx * 4 + 2][ty] = b.x;
    tt[tx * 4 + 3][ty] = b.y;
    __syncthreads();
    // write 32 d-rows x 32 s (uint2 per thread)
    __half2 c, d;
    c.x = tt[ty][tx * 4 + 0]; c.y = tt[ty][tx * 4 + 1];
    d.x = tt[ty][tx * 4 + 2]; d.y = tt[ty][tx * 4 + 3];
    uint2 o;
    o.x = *(uint32_t*)&c;
    o.y = *(uint32_t*)&d;
    *(uint2*)&V2[((size_t)h * DV + d0 + ty) * SEQ + s0 + tx * 4] = o;
}

// ---------------- RMSNorm -> fp16 (float4 loads, 4-half stores) ----------------
__global__ __launch_bounds__(256) void rmsnorm_h(
    const float* __restrict__ src, const float* __restrict__ gamma,
    __half* __restrict__ dst, int stride, int len)
{
    const int row = blockIdx.x;
    const float* x = src + (size_t)row * stride;
    const int len4 = len >> 2;
    float ss = 0.f;
    for (int i = threadIdx.x; i < len4; i += 256) {
        float4 v = ((const float4*)x)[i];
        ss += v.x * v.x + v.y * v.y + v.z * v.z + v.w * v.w;
    }
#pragma unroll
    for (int o = 16; o; o >>= 1) ss += __shfl_xor_sync(0xffffffffu, ss, o);
    __shared__ float ws[8]; __shared__ float s_inv;
    if ((threadIdx.x & 31) == 0) ws[threadIdx.x >> 5] = ss;
    __syncthreads();
    if (threadIdx.x == 0) {
        float t = 0.f;
#pragma unroll
        for (int i = 0; i < 8; i++) t += ws[i];
        s_inv = rsqrtf(t / (float)len + 1e-6f);
    }
    __syncthreads();
    const float inv = s_inv;
    __half* out = dst + (size_t)row * len;
    for (int i = threadIdx.x; i < len4; i += 256) {
        float4 v = ((const float4*)x)[i];
        float4 gm = ((const float4*)gamma)[i];
        __half2 a = __floats2half2_rn(v.x * gm.x * inv, v.y * gm.y * inv);
        __half2 b = __floats2half2_rn(v.z * gm.z * inv, v.w * gm.w * inv);
        uint2 o;
        o.x = *(uint32_t*)&a;
        o.y = *(uint32_t*)&b;
        *(uint2*)&out[i * 4] = o;
    }
}

// ---------------- RoPE + pack Q/K only (V handled by v_pack) ----------------
__global__ __launch_bounds__(192) void rope_qk(
    const __half* __restrict__ qp, const __half* __restrict__ kvp,
    const float* __restrict__ fused,
    __half* __restrict__ Q2, __half* __restrict__ K2)
{
    const int s = blockIdx.x, h = blockIdx.y, d = threadIdx.x;
    const float scale = 0.07216878364870323f; // 1/sqrt(192)
    float qv, kv;
    if (d < DN) {
        qv = __half2float(qp[(size_t)s * QB_N + h * DFULL + d]) * scale;
        kv = __half2float(kvp[(size_t)s * KVB_N + h * (DN + DV) + d]);
    } else {
        int j = d - DN, i = j & 31;
        float inv_freq = powf(10000.f, -(float)(2 * i) / 64.f);
        float sn, cs;
        sincosf((float)s * inv_freq, &sn, &cs);
        size_t qoff = (size_t)s * QB_N + h * DFULL + DN;
        float qpe = __half2float(qp[qoff + j]);
        float qrot = (j < 32) ? -__half2float(qp[qoff + j + 32])
                              :  __half2float(qp[qoff + j - 32]);
        size_t koff = (size_t)s * FUSED_NPAD + (QL + KL);
        float kpe = fused[koff + j];
        float krot = (j < 32) ? -fused[koff + j + 32] : fused[koff + j - 32];
        qv = (qpe * cs + qrot * sn) * scale;
        kv = kpe * cs + krot * sn;
    }
    Q2[((size_t)h * SEQ + s) * DFULL + d] = __float2half_rn(qv);
    K2[((size_t)h * SEQ + s) * DFULL + d] = __float2half_rn(kv);
}

// ---------------- launcher (multi-stream fork/join, capture-legal) ----------------
extern "C" void kernel_launch(void* const* d_in, const int* in_sizes, int n_in,
                              void* d_out, int out_size)
{
    const float* hidden     = (const float*)d_in[0];
    const float* w_kv_a     = (const float*)d_in[1];
    const float* q_a_gamma  = (const float*)d_in[2];
    const float* w_qb       = (const float*)d_in[3];
    const float* kv_a_gamma = (const float*)d_in[4];
    const float* w_kvb      = (const float*)d_in[5];
    const float* w_o        = (const float*)d_in[6];
    float* out = (float*)d_out;

    static float* fused = nullptr;
    static __half *qp, *kvp, *H2, *QN2, *KVN2, *ATTN2, *WKVA2, *WQB2, *WKVB2, *WO2, *Q2, *K2, *V2;
    static cudaStream_t sB, sC;
    static cudaEvent_t evRoot, evB, evG1, evC;
    if (!fused) {
        cudaGetSymbolAddress((void**)&fused, g_fused);
        cudaGetSymbolAddress((void**)&qp,    g_qp);
        cudaGetSymbolAddress((void**)&kvp,   g_kvp);
        cudaGetSymbolAddress((void**)&H2,    g_H2);
        cudaGetSymbolAddress((void**)&QN2,   g_QN2);
        cudaGetSymbolAddress((void**)&KVN2,  g_KVN2);
        cudaGetSymbolAddress((void**)&ATTN2, g_ATTN2);
        cudaGetSymbolAddress((void**)&WKVA2, g_WKVA2);
        cudaGetSymbolAddress((void**)&WQB2,  g_WQB2);
        cudaGetSymbolAddress((void**)&WKVB2, g_WKVB2);
        cudaGetSymbolAddress((void**)&WO2,   g_WO2);
        cudaGetSymbolAddress((void**)&Q2,    g_Q2);
        cudaGetSymbolAddress((void**)&K2,    g_K2);
        cudaGetSymbolAddress((void**)&V2,    g_V2);
        cudaFuncSetAttribute(gemm_fp16, cudaFuncAttributeMaxDynamicSharedMemorySize, GSMEM);
        cudaFuncSetAttribute(flash_mma, cudaFuncAttributeMaxDynamicSharedMemorySize, FSMEM);
        cudaStreamCreateWithFlags(&sB, cudaStreamNonBlocking);
        cudaStreamCreateWithFlags(&sC, cudaStreamNonBlocking);
        cudaEventCreateWithFlags(&evRoot, cudaEventDisableTiming);
        cudaEventCreateWithFlags(&evB,    cudaEventDisableTiming);
        cudaEventCreateWithFlags(&evG1,   cudaEventDisableTiming);
        cudaEventCreateWithFlags(&evC,    cudaEventDisableTiming);
    }

    // ---- fork: stream B does the GEMM1-independent weight transposes ----
    cudaEventRecord(evRoot, 0);
    cudaStreamWaitEvent(sB, evRoot, 0);
    transpose_w_h<<<dim3(QL / 32, QB_N / 32), 256, 0, sB>>>(w_qb, WQB2, QL, QB_N);
    transpose_w_h<<<dim3(KL / 32, KVB_N / 32), 256, 0, sB>>>(w_kvb, WKVB2, KL, KVB_N);
    transpose_w_h<<<dim3(HDIM / 32, HDIM / 32), 256, 0, sB>>>(w_o, WO2, HDIM, HDIM);
    cudaEventRecord(evB, sB);

    // ---- main stream: GEMM1 critical path ----
    cvt_act4<<<(SEQ * HDIM / 4 + 255) / 256, 256>>>(
        (const float4*)hidden, (uint2*)H2, SEQ * HDIM / 4);
    transpose_w_h<<<dim3(HDIM / 32, FUSED_REAL / 32), 256>>>(w_kv_a, WKVA2, HDIM, FUSED_REAL);
    gemm_fp16<<<dim3(FUSED_NPAD / 128, SEQ / 128), 256, GSMEM>>>(
        H2, WKVA2, fused, HDIM, HDIM, FUSED_NPAD, HDIM, 0);
    cudaEventRecord(evG1, 0);

    // ---- stream C: KV branch (rmsnorm_kv -> GEMM3 -> v_pack, fp16) ----
    cudaStreamWaitEvent(sC, evG1, 0);
    cudaStreamWaitEvent(sC, evB, 0);
    rmsnorm_h<<<SEQ, 256, 0, sC>>>(fused + QL, kv_a_gamma, KVN2, FUSED_NPAD, KL);
    gemm_fp16<<<dim3(KVB_N / 128, SEQ / 128), 256, GSMEM, sC>>>(
        KVN2, WKVB2, (float*)kvp, KL, KL, KVB_N, KL, 1);
    v_pack<<<dim3(SEQ / 32, DV / 32, NH), 256, 0, sC>>>(kvp, V2);
    cudaEventRecord(evC, sC);

    // ---- main stream: Q branch (fp16 out) ----
    rmsnorm_h<<<SEQ, 256>>>(fused, q_a_gamma, QN2, FUSED_NPAD, QL);
    cudaStreamWaitEvent(0, evB, 0);
    gemm_fp16<<<dim3(QB_N / 128, SEQ / 128), 256, GSMEM>>>(
        QN2, WQB2, (float*)qp, QL, QL, QB_N, QL, 1);

    // ---- join: rope needs qp (main) + kvp (stream C) ----
    cudaStreamWaitEvent(0, evC, 0);
    rope_qk<<<dim3(SEQ, NH), 192>>>(qp, kvp, fused, Q2, K2);

    // fused causal flash attention -> fp16 ATTN2
    flash_mma<<<dim3(SEQ / 128, NH), 256, FSMEM>>>(Q2, K2, V2, ATTN2);

    // out = attn @ w_o
    gemm_fp16<<<dim3(HDIM / 128, SEQ / 128), 256, GSMEM>>>(
        ATTN2, WO2, out, HDIM, HDIM, HDIM, HDIM, 0);
}

// round 16
// speedup vs baseline: 1.0903x; 1.0161x over previous
#include <cuda_runtime.h>
#include <cuda_fp16.h>
#include <math.h>
#include <stdint.h>

#define SEQ    2048
#define HDIM   2048
#define NH     16
#define DN     128
#define DR     64
#define DV     128
#define QL     1536
#define KL     512
#define DFULL  192
#define FUSED_NPAD 2176
#define FUSED_REAL 2112
#define QB_N   3072
#define KVB_N  4096

// ---------------- device scratch (zero-initialized) ----------------
__device__ float g_fused[SEQ * FUSED_NPAD];
__device__ __half g_qp[SEQ * QB_N];
__device__ __half g_kvp[SEQ * KVB_N];
__device__ float2 g_trig[SEQ * 32];             // cos/sin table
__device__ __half g_H2   [SEQ * HDIM];
__device__ __half g_QN2  [SEQ * QL];
__device__ __half g_KVN2 [SEQ * KL];
__device__ __half g_ATTN2[SEQ * HDIM];
__device__ __half g_WKVA2[FUSED_NPAD * HDIM];   // rows >= 2112 stay 0
__device__ __half g_WQB2 [QB_N * QL];
__device__ __half g_WKVB2[KVB_N * KL];
__device__ __half g_WO2  [HDIM * HDIM];
__device__ __half g_Q2 [NH * SEQ * DFULL];
__device__ __half g_K2 [NH * SEQ * DFULL];
__device__ __half g_V2 [NH * DV * SEQ];         // [h][d][s]

// ---------------- helpers ----------------
__device__ __forceinline__ uint32_t smem_u32(const void* p) {
    uint32_t a;
    asm("{ .reg .u64 t; cvta.to.shared.u64 t, %1; cvt.u32.u64 %0, t; }" : "=r"(a) : "l"(p));
    return a;
}
__device__ __forceinline__ void cp16(uint32_t dst, const void* src) {
    asm volatile("cp.async.cg.shared.global [%0], [%1], 16;" :: "r"(dst), "l"(src));
}
__device__ __forceinline__ void ldsm_x4(uint32_t* r, uint32_t a) {
    asm volatile("ldmatrix.sync.aligned.m8n8.x4.shared.b16 {%0,%1,%2,%3}, [%4];"
                 : "=r"(r[0]), "=r"(r[1]), "=r"(r[2]), "=r"(r[3]) : "r"(a));
}
__device__ __forceinline__ void mma16816(float* c, const uint32_t* a, uint32_t b0, uint32_t b1) {
    asm volatile(
        "mma.sync.aligned.m16n8k16.row.col.f32.f16.f16.f32 "
        "{%0,%1,%2,%3}, {%4,%5,%6,%7}, {%8,%9}, {%0,%1,%2,%3};"
        : "+f"(c[0]), "+f"(c[1]), "+f"(c[2]), "+f"(c[3])
        : "r"(a[0]), "r"(a[1]), "r"(a[2]), "r"(a[3]), "r"(b0), "r"(b1));
}

// ============================================================================
// fp16 GEMM: C = A B^T, K-major fp16 operands; fp32 or fp16 C (outHalf).
// ============================================================================
#define GSMEM (3 * 32768)

__global__ __launch_bounds__(256) void gemm_fp16(
    const __half* __restrict__ A,
    const __half* __restrict__ B,
    float* __restrict__ C,
    int lda, int ldb, int ldc, int K, int outHalf)
{
    const int n0 = blockIdx.x * 128;
    const int m0 = blockIdx.y * 128;
    const int ntiles = K >> 6;

    extern __shared__ char smraw[];
    const uint32_t s0 = smem_u32(smraw);

    const int tid = threadIdx.x;
    const int lane = tid & 31;
    const int wid = tid >> 5;
    const int wm = (wid & 1) * 64;
    const int wn = (wid >> 1) * 32;
    const int g = lane >> 2, t4 = lane & 3;

    const int ra = lane & 15;
    const int sega = (lane >> 4) & 1;
    const int rb = (lane >> 4) * 8 + (lane & 7);
    const int segb = (lane >> 3) & 1;
    uint32_t a_off[4], b_off[2];
#pragma unroll
    for (int mt = 0; mt < 4; mt++) a_off[mt] = (uint32_t)((wm + mt * 16 + ra) * 128);
#pragma unroll
    for (int p = 0; p < 2; p++) b_off[p] = (uint32_t)((wn + p * 16 + rb) * 128);
    const int a_swrow = ra & 7;
    const int b_swrow = rb & 7;

    float c[4][4][4];
#pragma unroll
    for (int i = 0; i < 4; i++)
#pragma unroll
        for (int j = 0; j < 4; j++)
#pragma unroll
            for (int e = 0; e < 4; e++) c[i][j][e] = 0.f;

    auto load_tile = [&](int i, int buf) {
        const __half* Ag = A + (size_t)m0 * lda + (i << 6);
        const __half* Bg = B + (size_t)n0 * ldb + (i << 6);
        const uint32_t da = s0 + buf * 32768;
        const uint32_t db = da + 16384;
#pragma unroll
        for (int t = 0; t < 4; t++) {
            int ch = tid + t * 256;
            int r = ch >> 3;
            int s = ch & 7;
            uint32_t sw = (uint32_t)(r * 128 + ((s ^ (r & 7)) << 4));
            cp16(da + sw, Ag + (size_t)r * lda + s * 8);
            cp16(db + sw, Bg + (size_t)r * ldb + s * 8);
        }
        asm volatile("cp.async.commit_group;");
    };

    load_tile(0, 0);
    if (ntiles > 1) load_tile(1, 1); else asm volatile("cp.async.commit_group;");

    for (int i = 0; i < ntiles; i++) {
        asm volatile("cp.async.wait_group 1;");
        __syncthreads();
        if (i + 2 < ntiles) load_tile(i + 2, (i + 2) % 3);
        else asm volatile("cp.async.commit_group;");

        const uint32_t ab = s0 + (i % 3) * 32768;
        const uint32_t bb = ab + 16384;
#pragma unroll
        for (int kc = 0; kc < 4; kc++) {
            const uint32_t ax = (uint32_t)(((kc * 2 + sega) ^ a_swrow) << 4);
            const uint32_t bx = (uint32_t)(((kc * 2 + segb) ^ b_swrow) << 4);
            uint32_t a[4][4], b[2][4];
#pragma unroll
            for (int mt = 0; mt < 4; mt++) ldsm_x4(a[mt], ab + a_off[mt] + ax);
#pragma unroll
            for (int p = 0; p < 2; p++) ldsm_x4(b[p], bb + b_off[p] + bx);
#pragma unroll
            for (int mt = 0; mt < 4; mt++) {
                mma16816(c[mt][0], a[mt], b[0][0], b[0][1]);
                mma16816(c[mt][1], a[mt], b[0][2], b[0][3]);
                mma16816(c[mt][2], a[mt], b[1][0], b[1][1]);
                mma16816(c[mt][3], a[mt], b[1][2], b[1][3]);
            }
        }
    }

    if (outHalf) {
        __half* Ch = (__half*)C;
#pragma unroll
        for (int mt = 0; mt < 4; mt++)
#pragma unroll
            for (int nt = 0; nt < 4; nt++) {
                int row = m0 + wm + mt * 16 + g;
                int col = n0 + wn + nt * 8 + t4 * 2;
                __half2 lo = __floats2half2_rn(c[mt][nt][0], c[mt][nt][1]);
                __half2 hi = __floats2half2_rn(c[mt][nt][2], c[mt][nt][3]);
                *(__half2*)&Ch[(size_t)row * ldc + col] = lo;
                *(__half2*)&Ch[(size_t)(row + 8) * ldc + col] = hi;
            }
    } else {
#pragma unroll
        for (int mt = 0; mt < 4; mt++)
#pragma unroll
            for (int nt = 0; nt < 4; nt++) {
                int row = m0 + wm + mt * 16 + g;
                int col = n0 + wn + nt * 8 + t4 * 2;
                *(float2*)&C[(size_t)row * ldc + col] = make_float2(c[mt][nt][0], c[mt][nt][1]);
                *(float2*)&C[(size_t)(row + 8) * ldc + col] = make_float2(c[mt][nt][2], c[mt][nt][3]);
            }
    }
}

// ============================================================================
// Fused flash attention (causal) — unified grid, big tiles first.
// ============================================================================
#define FSMEM (49152 + 2 * 24576 + 2 * 16384)   // 131072

__global__ __launch_bounds__(256) void flash_mma(
    const __half* __restrict__ Qg_, const __half* __restrict__ Kg_,
    const __half* __restrict__ Vg_, __half* __restrict__ O)
{
    const int qb = (int)(gridDim.x - 1) - (int)blockIdx.x;  // big first
    const int h = blockIdx.y;
    const int kend = 2 * qb + 2;

    extern __shared__ char sm[];
    const uint32_t sQ = smem_u32(sm);
    const uint32_t sK = sQ + 49152;
    const uint32_t sV = sK + 2 * 24576;

    const int tid = threadIdx.x, lane = tid & 31, w = tid >> 5;
    const int g = lane >> 2, t4 = lane & 3;

    const __half* Qg = Qg_ + ((size_t)h * SEQ + (size_t)qb * 128) * DFULL;
    const __half* Kg = Kg_ + (size_t)h * SEQ * DFULL;
    const __half* Vg = Vg_ + (size_t)h * DV * SEQ;

    {
#pragma unroll
        for (int t = 0; t < 12; t++) {
            int ch = tid + t * 256;
            int r = ch / 24, s = ch % 24;
            uint32_t sw = (uint32_t)(r * 384 + ((s ^ (r & 7)) << 4));
            cp16(sQ + sw, Qg + r * DFULL + s * 8);
        }
        asm volatile("cp.async.commit_group;");
    }
    auto load_kv = [&](int kb, int buf) {
        const __half* Kt = Kg + (size_t)kb * 64 * DFULL;
#pragma unroll
        for (int t = 0; t < 6; t++) {
            int ch = tid + t * 256;
            int r = ch / 24, s = ch % 24;
            uint32_t sw = (uint32_t)(r * 384 + ((s ^ (r & 7)) << 4));
            cp16(sK + buf * 24576 + sw, Kt + r * DFULL + s * 8);
        }
        const __half* Vt = Vg + kb * 64;
#pragma unroll
        for (int t = 0; t < 4; t++) {
            int ch = tid + t * 256;
            int r = ch >> 3, s = ch & 7;
            uint32_t sw = (uint32_t)(r * 128 + ((s ^ (r & 7)) << 4));
            cp16(sV + buf * 16384 + sw, Vt + (size_t)r * SEQ + s * 8);
        }
        asm volatile("cp.async.commit_group;");
    };
    load_kv(0, 0);
    load_kv(1, 1);
    asm volatile("cp.async.wait_group 1;");
    __syncthreads();

    const int ra = lane & 15, sega = (lane >> 4) & 1;
    const uint32_t q_off = (uint32_t)((w * 16 + ra) * 384);
    const int a_swrow = ra & 7;
    const int rb = ((lane >> 4) << 3) + (lane & 7), segb = (lane >> 3) & 1;
    const int b_swrow = rb & 7;

    float m0 = -INFINITY, m1 = -INFINITY, l0 = 0.f, l1 = 0.f;
    float o[16][4];
#pragma unroll
    for (int i = 0; i < 16; i++)
#pragma unroll
        for (int e = 0; e < 4; e++) o[i][e] = 0.f;

    for (int kb = 0; kb < kend; kb++) {
        const uint32_t kbuf = sK + (kb & 1) * 24576;
        const uint32_t vbuf = sV + (kb & 1) * 16384;

        float S[8][4];
#pragma unroll
        for (int j = 0; j < 8; j++)
#pragma unroll
            for (int e = 0; e < 4; e++) S[j][e] = 0.f;

#pragma unroll
        for (int ks = 0; ks < 12; ks++) {
            uint32_t a[4];
            ldsm_x4(a, sQ + q_off + (uint32_t)(((ks * 2 + sega) ^ a_swrow) << 4));
            const uint32_t bx = (uint32_t)(((ks * 2 + segb) ^ b_swrow) << 4);
#pragma unroll
            for (int nt = 0; nt < 4; nt++) {
                uint32_t b[4];
                ldsm_x4(b, kbuf + (uint32_t)((nt * 16 + rb) * 384) + bx);
                mma16816(S[nt * 2],     a, b[0], b[1]);
                mma16816(S[nt * 2 + 1], a, b[2], b[3]);
            }
        }

        if (kb >= 2 * qb) {
            const int row0 = qb * 128 + w * 16 + g;
            const int colb = kb * 64 + t4 * 2;
#pragma unroll
            for (int j = 0; j < 8; j++) {
#pragma unroll
                for (int e = 0; e < 2; e++) {
                    int col = colb + j * 8 + e;
                    if (col > row0) S[j][e] = -INFINITY;
                    if (col > row0 + 8) S[j][2 + e] = -INFINITY;
                }
            }
        }

        float mx0 = -INFINITY, mx1 = -INFINITY;
#pragma unroll
        for (int j = 0; j < 8; j++) {
            mx0 = fmaxf(mx0, fmaxf(S[j][0], S[j][1]));
            mx1 = fmaxf(mx1, fmaxf(S[j][2], S[j][3]));
        }
        mx0 = fmaxf(mx0, __shfl_xor_sync(0xffffffffu, mx0, 1));
        mx0 = fmaxf(mx0, __shfl_xor_sync(0xffffffffu, mx0, 2));
        mx1 = fmaxf(mx1, __shfl_xor_sync(0xffffffffu, mx1, 1));
        mx1 = fmaxf(mx1, __shfl_xor_sync(0xffffffffu, mx1, 2));
        const float mn0 = fmaxf(m0, mx0), mn1 = fmaxf(m1, mx1);
        const float c0 = __expf(m0 - mn0), c1 = __expf(m1 - mn1);
        float s0 = 0.f, s1 = 0.f;
#pragma unroll
        for (int j = 0; j < 8; j++) {
            S[j][0] = __expf(S[j][0] - mn0);
            S[j][1] = __expf(S[j][1] - mn0);
            S[j][2] = __expf(S[j][2] - mn1);
            S[j][3] = __expf(S[j][3] - mn1);
            s0 += S[j][0] + S[j][1];
            s1 += S[j][2] + S[j][3];
        }
        s0 += __shfl_xor_sync(0xffffffffu, s0, 1);
        s0 += __shfl_xor_sync(0xffffffffu, s0, 2);
        s1 += __shfl_xor_sync(0xffffffffu, s1, 1);
        s1 += __shfl_xor_sync(0xffffffffu, s1, 2);
        l0 = l0 * c0 + s0;
        l1 = l1 * c1 + s1;
        m0 = mn0; m1 = mn1;
#pragma unroll
        for (int i = 0; i < 16; i++) {
            o[i][0] *= c0; o[i][1] *= c0;
            o[i][2] *= c1; o[i][3] *= c1;
        }

        uint32_t ap[4][4];
#pragma unroll
        for (int i = 0; i < 4; i++) {
            __half2 h0 = __floats2half2_rn(S[2 * i][0], S[2 * i][1]);
            __half2 h1 = __floats2half2_rn(S[2 * i][2], S[2 * i][3]);
            __half2 h2 = __floats2half2_rn(S[2 * i + 1][0], S[2 * i + 1][1]);
            __half2 h3 = __floats2half2_rn(S[2 * i + 1][2], S[2 * i + 1][3]);
            ap[i][0] = *(uint32_t*)&h0;
            ap[i][1] = *(uint32_t*)&h1;
            ap[i][2] = *(uint32_t*)&h2;
            ap[i][3] = *(uint32_t*)&h3;
        }

#pragma unroll
        for (int i = 0; i < 4; i++) {
            const uint32_t vx = (uint32_t)(((i * 2 + segb) ^ b_swrow) << 4);
#pragma unroll
            for (int nt = 0; nt < 8; nt++) {
                uint32_t b[4];
                ldsm_x4(b, vbuf + (uint32_t)((nt * 16 + rb) * 128) + vx);
                mma16816(o[nt * 2],     ap[i], b[0], b[1]);
                mma16816(o[nt * 2 + 1], ap[i], b[2], b[3]);
            }
        }

        __syncthreads();
        if (kb + 2 < kend) load_kv(kb + 2, kb & 1);
        else asm volatile("cp.async.commit_group;");
        asm volatile("cp.async.wait_group 1;");
        __syncthreads();
    }

    const float inv0 = 1.f / l0, inv1 = 1.f / l1;
    const int r0 = qb * 128 + w * 16 + g;
#pragma unroll
    for (int nt = 0; nt < 16; nt++) {
        const int col = h * DV + nt * 8 + t4 * 2;
        __half2 lo = __floats2half2_rn(o[nt][0] * inv0, o[nt][1] * inv0);
        __half2 hi = __floats2half2_rn(o[nt][2] * inv1, o[nt][3] * inv1);
        *(__half2*)&O[(size_t)r0 * HDIM + col] = lo;
        *(__half2*)&O[(size_t)(r0 + 8) * HDIM + col] = hi;
    }
}

// ---------------- fp32 -> fp16 convert (4/thread) ----------------
__global__ __launch_bounds__(256) void cvt_act4(
    const float4* __restrict__ X, uint2* __restrict__ X2, int total4)
{
    int i = blockIdx.x * 256 + threadIdx.x;
    if (i >= total4) return;
    float4 v = X[i];
    __half2 a = __floats2half2_rn(v.x, v.y);
    __half2 b = __floats2half2_rn(v.z, v.w);
    uint2 o;
    o.x = *(uint32_t*)&a;
    o.y = *(uint32_t*)&b;
    X2[i] = o;
}

// ---------------- weight transpose+convert (vectorized): W[K,N] -> Wt[N,K] fp16 ----------------
__global__ __launch_bounds__(256) void transpose_w_h(
    const float* __restrict__ W, __half* __restrict__ Wt, int K, int N)
{
    __shared__ __half tt[32][40];
    const int kb = blockIdx.x * 32, nb = blockIdx.y * 32;
    const int tx = threadIdx.x & 7, ty = threadIdx.x >> 3;
    float4 v = *(const float4*)&W[(size_t)(kb + ty) * N + nb + tx * 4];
    tt[tx * 4 + 0][ty] = __float2half_rn(v.x);
    tt[tx * 4 + 1][ty] = __float2half_rn(v.y);
    tt[tx * 4 + 2][ty] = __float2half_rn(v.z);
    tt[tx * 4 + 3][ty] = __float2half_rn(v.w);
    __syncthreads();
    uint2 o;
    __half2 a, b;
    a.x = tt[ty][tx * 4 + 0]; a.y = tt[ty][tx * 4 + 1];
    b.x = tt[ty][tx * 4 + 2]; b.y = tt[ty][tx * 4 + 3];
    o.x = *(uint32_t*)&a;
    o.y = *(uint32_t*)&b;
    *(uint2*)&Wt[(size_t)(nb + ty) * K + kb + tx * 4] = o;
}

// ---------------- RoPE trig table: g_trig[s*32+i] = (cos, sin)(s * 10000^(-i/32)) ----------------
__global__ __launch_bounds__(256) void rope_table(float2* __restrict__ trig)
{
    int idx = blockIdx.x * 256 + threadIdx.x;
    if (idx >= SEQ * 32) return;
    int s = idx >> 5, i = idx & 31;
    float inv_freq = powf(10000.f, -(float)(2 * i) / 64.f);
    float sn, cs;
    sincosf((float)s * inv_freq, &sn, &cs);
    trig[idx] = make_float2(cs, sn);
}

// ---------------- V pack: kvp[s][h*256+128+d] -> V2[h][d][s], coalesced ----------------
__global__ __launch_bounds__(256) void v_pack(
    const __half* __restrict__ kvp, __half* __restrict__ V2)
{
    __shared__ __half tt[32][40];
    const int s0 = blockIdx.x * 32;
    const int d0 = blockIdx.y * 32;
    const int h  = blockIdx.z;
    const int tx = threadIdx.x & 7, ty = threadIdx.x >> 3;
    uint2 v = *(const uint2*)&kvp[(size_t)(s0 + ty) * KVB_N + h * (DN + DV) + DN + d0 + tx * 4];
    __half2 a = *(__half2*)&v.x, b = *(__half2*)&v.y;
    tt[tx * 4 + 0][ty] = a.x;
    tt[tx * 4 + 1][ty] = a.y;
    tt[tx * 4 + 2][ty] = b.x;
    tt[tx * 4 + 3][ty] = b.y;
    __syncthreads();
    __half2 c, d;
    c.x = tt[ty][tx * 4 + 0]; c.y = tt[ty][tx * 4 + 1];
    d.x = tt[ty][tx * 4 + 2]; d.y = tt[ty][tx * 4 + 3];
    uint2 o;
    o.x = *(uint32_t*)&c;
    o.y = *(uint32_t*)&d;
    *(uint2*)&V2[((size_t)h * DV + d0 + ty) * SEQ + s0 + tx * 4] = o;
}

// ---------------- RMSNorm -> fp16 (float4 loads, 4-half stores) ----------------
__global__ __launch_bounds__(256) void rmsnorm_h(
    const float* __restrict__ src, const float* __restrict__ gamma,
    __half* __restrict__ dst, int stride, int len)
{
    const int row = blockIdx.x;
    const float* x = src + (size_t)row * stride;
    const int len4 = len >> 2;
    float ss = 0.f;
    for (int i = threadIdx.x; i < len4; i += 256) {
        float4 v = ((const float4*)x)[i];
        ss += v.x * v.x + v.y * v.y + v.z * v.z + v.w * v.w;
    }
#pragma unroll
    for (int o = 16; o; o >>= 1) ss += __shfl_xor_sync(0xffffffffu, ss, o);
    __shared__ float ws[8]; __shared__ float s_inv;
    if ((threadIdx.x & 31) == 0) ws[threadIdx.x >> 5] = ss;
    __syncthreads();
    if (threadIdx.x == 0) {
        float t = 0.f;
#pragma unroll
        for (int i = 0; i < 8; i++) t += ws[i];
        s_inv = rsqrtf(t / (float)len + 1e-6f);
    }
    __syncthreads();
    const float inv = s_inv;
    __half* out = dst + (size_t)row * len;
    for (int i = threadIdx.x; i < len4; i += 256) {
        float4 v = ((const float4*)x)[i];
        float4 gm = ((const float4*)gamma)[i];
        __half2 a = __floats2half2_rn(v.x * gm.x * inv, v.y * gm.y * inv);
        __half2 b = __floats2half2_rn(v.z * gm.z * inv, v.w * gm.w * inv);
        uint2 o;
        o.x = *(uint32_t*)&a;
        o.y = *(uint32_t*)&b;
        *(uint2*)&out[i * 4] = o;
    }
}

// ---------------- RoPE + pack Q/K (table-based trig) ----------------
__global__ __launch_bounds__(192) void rope_qk(
    const __half* __restrict__ qp, const __half* __restrict__ kvp,
    const float* __restrict__ fused, const float2* __restrict__ trig,
    __half* __restrict__ Q2, __half* __restrict__ K2)
{
    const int s = blockIdx.x, h = blockIdx.y, d = threadIdx.x;
    const float scale = 0.07216878364870323f; // 1/sqrt(192)
    float qv, kv;
    if (d < DN) {
        qv = __half2float(qp[(size_t)s * QB_N + h * DFULL + d]) * scale;
        kv = __half2float(kvp[(size_t)s * KVB_N + h * (DN + DV) + d]);
    } else {
        int j = d - DN, i = j & 31;
        float2 cssn = trig[s * 32 + i];
        const float cs = cssn.x, sn = cssn.y;
        size_t qoff = (size_t)s * QB_N + h * DFULL + DN;
        float qpe = __half2float(qp[qoff + j]);
        float qrot = (j < 32) ? -__half2float(qp[qoff + j + 32])
                              :  __half2float(qp[qoff + j - 32]);
        size_t koff = (size_t)s * FUSED_NPAD + (QL + KL);
        float kpe = fused[koff + j];
        float krot = (j < 32) ? -fused[koff + j + 32] : fused[koff + j - 32];
        qv = (qpe * cs + qrot * sn) * scale;
        kv = kpe * cs + krot * sn;
    }
    Q2[((size_t)h * SEQ + s) * DFULL + d] = __float2half_rn(qv);
    K2[((size_t)h * SEQ + s) * DFULL + d] = __float2half_rn(kv);
}

// ---------------- launcher (multi-stream fork/join, capture-legal) ----------------
extern "C" void kernel_launch(void* const* d_in, const int* in_sizes, int n_in,
                              void* d_out, int out_size)
{
    const float* hidden     = (const float*)d_in[0];
    const float* w_kv_a     = (const float*)d_in[1];
    const float* q_a_gamma  = (const float*)d_in[2];
    const float* w_qb       = (const float*)d_in[3];
    const float* kv_a_gamma = (const float*)d_in[4];
    const float* w_kvb      = (const float*)d_in[5];
    const float* w_o        = (const float*)d_in[6];
    float* out = (float*)d_out;

    static float* fused = nullptr;
    static float2* trig;
    static __half *qp, *kvp, *H2, *QN2, *KVN2, *ATTN2, *WKVA2, *WQB2, *WKVB2, *WO2, *Q2, *K2, *V2;
    static cudaStream_t sB, sC;
    static cudaEvent_t evRoot, evWA, evB, evG1, evC;
    if (!fused) {
        cudaGetSymbolAddress((void**)&fused, g_fused);
        cudaGetSymbolAddress((void**)&qp,    g_qp);
        cudaGetSymbolAddress((void**)&kvp,   g_kvp);
        cudaGetSymbolAddress((void**)&trig,  g_trig);
        cudaGetSymbolAddress((void**)&H2,    g_H2);
        cudaGetSymbolAddress((void**)&QN2,   g_QN2);
        cudaGetSymbolAddress((void**)&KVN2,  g_KVN2);
        cudaGetSymbolAddress((void**)&ATTN2, g_ATTN2);
        cudaGetSymbolAddress((void**)&WKVA2, g_WKVA2);
        cudaGetSymbolAddress((void**)&WQB2,  g_WQB2);
        cudaGetSymbolAddress((void**)&WKVB2, g_WKVB2);
        cudaGetSymbolAddress((void**)&WO2,   g_WO2);
        cudaGetSymbolAddress((void**)&Q2,    g_Q2);
        cudaGetSymbolAddress((void**)&K2,    g_K2);
        cudaGetSymbolAddress((void**)&V2,    g_V2);
        cudaFuncSetAttribute(gemm_fp16, cudaFuncAttributeMaxDynamicSharedMemorySize, GSMEM);
        cudaFuncSetAttribute(flash_mma, cudaFuncAttributeMaxDynamicSharedMemorySize, FSMEM);
        cudaStreamCreateWithFlags(&sB, cudaStreamNonBlocking);
        cudaStreamCreateWithFlags(&sC, cudaStreamNonBlocking);
        cudaEventCreateWithFlags(&evRoot, cudaEventDisableTiming);
        cudaEventCreateWithFlags(&evWA,   cudaEventDisableTiming);
        cudaEventCreateWithFlags(&evB,    cudaEventDisableTiming);
        cudaEventCreateWithFlags(&evG1,   cudaEventDisableTiming);
        cudaEventCreateWithFlags(&evC,    cudaEventDisableTiming);
    }

    // ---- fork: stream B — WKVA transpose FIRST (GEMM1 gate), then the rest ----
    cudaEventRecord(evRoot, 0);
    cudaStreamWaitEvent(sB, evRoot, 0);
    transpose_w_h<<<dim3(HDIM / 32, FUSED_REAL / 32), 256, 0, sB>>>(w_kv_a, WKVA2, HDIM, FUSED_REAL);
    cudaEventRecord(evWA, sB);
    transpose_w_h<<<dim3(QL / 32, QB_N / 32), 256, 0, sB>>>(w_qb, WQB2, QL, QB_N);
    transpose_w_h<<<dim3(KL / 32, KVB_N / 32), 256, 0, sB>>>(w_kvb, WKVB2, KL, KVB_N);
    transpose_w_h<<<dim3(HDIM / 32, HDIM / 32), 256, 0, sB>>>(w_o, WO2, HDIM, HDIM);
    rope_table<<<(SEQ * 32 + 255) / 256, 256, 0, sB>>>(trig);
    cudaEventRecord(evB, sB);

    // ---- main stream: cvt runs concurrently with WKVA transpose ----
    cvt_act4<<<(SEQ * HDIM / 4 + 255) / 256, 256>>>(
        (const float4*)hidden, (uint2*)H2, SEQ * HDIM / 4);
    cudaStreamWaitEvent(0, evWA, 0);
    gemm_fp16<<<dim3(FUSED_NPAD / 128, SEQ / 128), 256, GSMEM>>>(
        H2, WKVA2, fused, HDIM, HDIM, FUSED_NPAD, HDIM, 0);
    cudaEventRecord(evG1, 0);

    // ---- stream C: KV branch (rmsnorm_kv -> GEMM3 -> v_pack, fp16) ----
    cudaStreamWaitEvent(sC, evG1, 0);
    cudaStreamWaitEvent(sC, evB, 0);
    rmsnorm_h<<<SEQ, 256, 0, sC>>>(fused + QL, kv_a_gamma, KVN2, FUSED_NPAD, KL);
    gemm_fp16<<<dim3(KVB_N / 128, SEQ / 128), 256, GSMEM, sC>>>(
        KVN2, WKVB2, (float*)kvp, KL, KL, KVB_N, KL, 1);
    v_pack<<<dim3(SEQ / 32, DV / 32, NH), 256, 0, sC>>>(kvp, V2);
    cudaEventRecord(evC, sC);

    // ---- main stream: Q branch (fp16 out) ----
    rmsnorm_h<<<SEQ, 256>>>(fused, q_a_gamma, QN2, FUSED_NPAD, QL);
    cudaStreamWaitEvent(0, evB, 0);
    gemm_fp16<<<dim3(QB_N / 128, SEQ / 128), 256, GSMEM>>>(
        QN2, WQB2, (float*)qp, QL, QL, QB_N, QL, 1);

    // ---- join: rope needs qp (main) + kvp (stream C) + trig (evB) ----
    cudaStreamWaitEvent(0, evC, 0);
    rope_qk<<<dim3(SEQ, NH), 192>>>(qp, kvp, fused, trig, Q2, K2);

    // fused causal flash attention -> fp16 ATTN2
    flash_mma<<<dim3(SEQ / 128, NH), 256, FSMEM>>>(Q2, K2, V2, ATTN2);

    // out = attn @ w_o
    gemm_fp16<<<dim3(HDIM / 128, SEQ / 128), 256, GSMEM>>>(
        ATTN2, WO2, out, HDIM, HDIM, HDIM, HDIM, 0);
}

// round 17
// speedup vs baseline: 1.1112x; 1.0191x over previous
#include <cuda_runtime.h>
#include <cuda_fp16.h>
#include <math.h>
#include <stdint.h>

#define SEQ    2048
#define HDIM   2048
#define NH     16
#define DN     128
#define DR     64
#define DV     128
#define QL     1536
#define KL     512
#define DFULL  192
#define FUSED_NPAD 2176
#define FUSED_REAL 2112
#define QB_N   3072
#define KVB_N  4096

// ---------------- device scratch (zero-initialized) ----------------
__device__ float g_fused[SEQ * FUSED_NPAD];
__device__ __half g_qp[SEQ * QB_N];
__device__ __half g_kvp[SEQ * KVB_N];
__device__ float2 g_trig[SEQ * 32];             // cos/sin table
__device__ __half g_H2   [SEQ * HDIM];
__device__ __half g_QN2  [SEQ * QL];
__device__ __half g_KVN2 [SEQ * KL];
__device__ __half g_ATTN2[SEQ * HDIM];
__device__ __half g_WKVA2[FUSED_NPAD * HDIM];   // rows >= 2112 stay 0
__device__ __half g_WQB2 [QB_N * QL];
__device__ __half g_WKVB2[KVB_N * KL];
__device__ __half g_WO2  [HDIM * HDIM];
__device__ __half g_Q2 [NH * SEQ * DFULL];
__device__ __half g_K2 [NH * SEQ * DFULL];
__device__ __half g_V2 [NH * DV * SEQ];         // [h][d][s]

// ---------------- helpers ----------------
__device__ __forceinline__ uint32_t smem_u32(const void* p) {
    uint32_t a;
    asm("{ .reg .u64 t; cvta.to.shared.u64 t, %1; cvt.u32.u64 %0, t; }" : "=r"(a) : "l"(p));
    return a;
}
__device__ __forceinline__ void cp16(uint32_t dst, const void* src) {
    asm volatile("cp.async.cg.shared.global [%0], [%1], 16;" :: "r"(dst), "l"(src));
}
__device__ __forceinline__ void ldsm_x4(uint32_t* r, uint32_t a) {
    asm volatile("ldmatrix.sync.aligned.m8n8.x4.shared.b16 {%0,%1,%2,%3}, [%4];"
                 : "=r"(r[0]), "=r"(r[1]), "=r"(r[2]), "=r"(r[3]) : "r"(a));
}
__device__ __forceinline__ void mma16816(float* c, const uint32_t* a, uint32_t b0, uint32_t b1) {
    asm volatile(
        "mma.sync.aligned.m16n8k16.row.col.f32.f16.f16.f32 "
        "{%0,%1,%2,%3}, {%4,%5,%6,%7}, {%8,%9}, {%0,%1,%2,%3};"
        : "+f"(c[0]), "+f"(c[1]), "+f"(c[2]), "+f"(c[3])
        : "r"(a[0]), "r"(a[1]), "r"(a[2]), "r"(a[3]), "r"(b0), "r"(b1));
}

// ============================================================================
// fp16 GEMM: C = A B^T, K-major fp16 operands; fp32 or fp16 C (outHalf).
// ============================================================================
#define GSMEM (3 * 32768)

__global__ __launch_bounds__(256) void gemm_fp16(
    const __half* __restrict__ A,
    const __half* __restrict__ B,
    float* __restrict__ C,
    int lda, int ldb, int ldc, int K, int outHalf)
{
    const int n0 = blockIdx.x * 128;
    const int m0 = blockIdx.y * 128;
    const int ntiles = K >> 6;

    extern __shared__ char smraw[];
    const uint32_t s0 = smem_u32(smraw);

    const int tid = threadIdx.x;
    const int lane = tid & 31;
    const int wid = tid >> 5;
    const int wm = (wid & 1) * 64;
    const int wn = (wid >> 1) * 32;
    const int g = lane >> 2, t4 = lane & 3;

    const int ra = lane & 15;
    const int sega = (lane >> 4) & 1;
    const int rb = (lane >> 4) * 8 + (lane & 7);
    const int segb = (lane >> 3) & 1;
    uint32_t a_off[4], b_off[2];
#pragma unroll
    for (int mt = 0; mt < 4; mt++) a_off[mt] = (uint32_t)((wm + mt * 16 + ra) * 128);
#pragma unroll
    for (int p = 0; p < 2; p++) b_off[p] = (uint32_t)((wn + p * 16 + rb) * 128);
    const int a_swrow = ra & 7;
    const int b_swrow = rb & 7;

    float c[4][4][4];
#pragma unroll
    for (int i = 0; i < 4; i++)
#pragma unroll
        for (int j = 0; j < 4; j++)
#pragma unroll
            for (int e = 0; e < 4; e++) c[i][j][e] = 0.f;

    auto load_tile = [&](int i, int buf) {
        const __half* Ag = A + (size_t)m0 * lda + (i << 6);
        const __half* Bg = B + (size_t)n0 * ldb + (i << 6);
        const uint32_t da = s0 + buf * 32768;
        const uint32_t db = da + 16384;
#pragma unroll
        for (int t = 0; t < 4; t++) {
            int ch = tid + t * 256;
            int r = ch >> 3;
            int s = ch & 7;
            uint32_t sw = (uint32_t)(r * 128 + ((s ^ (r & 7)) << 4));
            cp16(da + sw, Ag + (size_t)r * lda + s * 8);
            cp16(db + sw, Bg + (size_t)r * ldb + s * 8);
        }
        asm volatile("cp.async.commit_group;");
    };

    load_tile(0, 0);
    if (ntiles > 1) load_tile(1, 1); else asm volatile("cp.async.commit_group;");

    for (int i = 0; i < ntiles; i++) {
        asm volatile("cp.async.wait_group 1;");
        __syncthreads();
        if (i + 2 < ntiles) load_tile(i + 2, (i + 2) % 3);
        else asm volatile("cp.async.commit_group;");

        const uint32_t ab = s0 + (i % 3) * 32768;
        const uint32_t bb = ab + 16384;
#pragma unroll
        for (int kc = 0; kc < 4; kc++) {
            const uint32_t ax = (uint32_t)(((kc * 2 + sega) ^ a_swrow) << 4);
            const uint32_t bx = (uint32_t)(((kc * 2 + segb) ^ b_swrow) << 4);
            uint32_t a[4][4], b[2][4];
#pragma unroll
            for (int mt = 0; mt < 4; mt++) ldsm_x4(a[mt], ab + a_off[mt] + ax);
#pragma unroll
            for (int p = 0; p < 2; p++) ldsm_x4(b[p], bb + b_off[p] + bx);
#pragma unroll
            for (int mt = 0; mt < 4; mt++) {
                mma16816(c[mt][0], a[mt], b[0][0], b[0][1]);
                mma16816(c[mt][1], a[mt], b[0][2], b[0][3]);
                mma16816(c[mt][2], a[mt], b[1][0], b[1][1]);
                mma16816(c[mt][3], a[mt], b[1][2], b[1][3]);
            }
        }
    }

    if (outHalf) {
        __half* Ch = (__half*)C;
#pragma unroll
        for (int mt = 0; mt < 4; mt++)
#pragma unroll
            for (int nt = 0; nt < 4; nt++) {
                int row = m0 + wm + mt * 16 + g;
                int col = n0 + wn + nt * 8 + t4 * 2;
                __half2 lo = __floats2half2_rn(c[mt][nt][0], c[mt][nt][1]);
                __half2 hi = __floats2half2_rn(c[mt][nt][2], c[mt][nt][3]);
                *(__half2*)&Ch[(size_t)row * ldc + col] = lo;
                *(__half2*)&Ch[(size_t)(row + 8) * ldc + col] = hi;
            }
    } else {
#pragma unroll
        for (int mt = 0; mt < 4; mt++)
#pragma unroll
            for (int nt = 0; nt < 4; nt++) {
                int row = m0 + wm + mt * 16 + g;
                int col = n0 + wn + nt * 8 + t4 * 2;
                *(float2*)&C[(size_t)row * ldc + col] = make_float2(c[mt][nt][0], c[mt][nt][1]);
                *(float2*)&C[(size_t)(row + 8) * ldc + col] = make_float2(c[mt][nt][2], c[mt][nt][3]);
            }
    }
}

// ============================================================================
// Fused flash attention (causal) — unified grid, big tiles first.
// ============================================================================
#define FSMEM (49152 + 2 * 24576 + 2 * 16384)   // 131072

__global__ __launch_bounds__(256) void flash_mma(
    const __half* __restrict__ Qg_, const __half* __restrict__ Kg_,
    const __half* __restrict__ Vg_, __half* __restrict__ O)
{
    const int qb = (int)(gridDim.x - 1) - (int)blockIdx.x;  // big first
    const int h = blockIdx.y;
    const int kend = 2 * qb + 2;

    extern __shared__ char sm[];
    const uint32_t sQ = smem_u32(sm);
    const uint32_t sK = sQ + 49152;
    const uint32_t sV = sK + 2 * 24576;

    const int tid = threadIdx.x, lane = tid & 31, w = tid >> 5;
    const int g = lane >> 2, t4 = lane & 3;

    const __half* Qg = Qg_ + ((size_t)h * SEQ + (size_t)qb * 128) * DFULL;
    const __half* Kg = Kg_ + (size_t)h * SEQ * DFULL;
    const __half* Vg = Vg_ + (size_t)h * DV * SEQ;

    {
#pragma unroll
        for (int t = 0; t < 12; t++) {
            int ch = tid + t * 256;
            int r = ch / 24, s = ch % 24;
            uint32_t sw = (uint32_t)(r * 384 + ((s ^ (r & 7)) << 4));
            cp16(sQ + sw, Qg + r * DFULL + s * 8);
        }
        asm volatile("cp.async.commit_group;");
    }
    auto load_kv = [&](int kb, int buf) {
        const __half* Kt = Kg + (size_t)kb * 64 * DFULL;
#pragma unroll
        for (int t = 0; t < 6; t++) {
            int ch = tid + t * 256;
            int r = ch / 24, s = ch % 24;
            uint32_t sw = (uint32_t)(r * 384 + ((s ^ (r & 7)) << 4));
            cp16(sK + buf * 24576 + sw, Kt + r * DFULL + s * 8);
        }
        const __half* Vt = Vg + kb * 64;
#pragma unroll
        for (int t = 0; t < 4; t++) {
            int ch = tid + t * 256;
            int r = ch >> 3, s = ch & 7;
            uint32_t sw = (uint32_t)(r * 128 + ((s ^ (r & 7)) << 4));
            cp16(sV + buf * 16384 + sw, Vt + (size_t)r * SEQ + s * 8);
        }
        asm volatile("cp.async.commit_group;");
    };
    load_kv(0, 0);
    load_kv(1, 1);
    asm volatile("cp.async.wait_group 1;");
    __syncthreads();

    const int ra = lane & 15, sega = (lane >> 4) & 1;
    const uint32_t q_off = (uint32_t)((w * 16 + ra) * 384);
    const int a_swrow = ra & 7;
    const int rb = ((lane >> 4) << 3) + (lane & 7), segb = (lane >> 3) & 1;
    const int b_swrow = rb & 7;

    float m0 = -INFINITY, m1 = -INFINITY, l0 = 0.f, l1 = 0.f;
    float o[16][4];
#pragma unroll
    for (int i = 0; i < 16; i++)
#pragma unroll
        for (int e = 0; e < 4; e++) o[i][e] = 0.f;

    for (int kb = 0; kb < kend; kb++) {
        const uint32_t kbuf = sK + (kb & 1) * 24576;
        const uint32_t vbuf = sV + (kb & 1) * 16384;

        float S[8][4];
#pragma unroll
        for (int j = 0; j < 8; j++)
#pragma unroll
            for (int e = 0; e < 4; e++) S[j][e] = 0.f;

#pragma unroll
        for (int ks = 0; ks < 12; ks++) {
            uint32_t a[4];
            ldsm_x4(a, sQ + q_off + (uint32_t)(((ks * 2 + sega) ^ a_swrow) << 4));
            const uint32_t bx = (uint32_t)(((ks * 2 + segb) ^ b_swrow) << 4);
#pragma unroll
            for (int nt = 0; nt < 4; nt++) {
                uint32_t b[4];
                ldsm_x4(b, kbuf + (uint32_t)((nt * 16 + rb) * 384) + bx);
                mma16816(S[nt * 2],     a, b[0], b[1]);
                mma16816(S[nt * 2 + 1], a, b[2], b[3]);
            }
        }

        if (kb >= 2 * qb) {
            const int row0 = qb * 128 + w * 16 + g;
            const int colb = kb * 64 + t4 * 2;
#pragma unroll
            for (int j = 0; j < 8; j++) {
#pragma unroll
                for (int e = 0; e < 2; e++) {
                    int col = colb + j * 8 + e;
                    if (col > row0) S[j][e] = -INFINITY;
                    if (col > row0 + 8) S[j][2 + e] = -INFINITY;
                }
            }
        }

        float mx0 = -INFINITY, mx1 = -INFINITY;
#pragma unroll
        for (int j = 0; j < 8; j++) {
            mx0 = fmaxf(mx0, fmaxf(S[j][0], S[j][1]));
            mx1 = fmaxf(mx1, fmaxf(S[j][2], S[j][3]));
        }
        mx0 = fmaxf(mx0, __shfl_xor_sync(0xffffffffu, mx0, 1));
        mx0 = fmaxf(mx0, __shfl_xor_sync(0xffffffffu, mx0, 2));
        mx1 = fmaxf(mx1, __shfl_xor_sync(0xffffffffu, mx1, 1));
        mx1 = fmaxf(mx1, __shfl_xor_sync(0xffffffffu, mx1, 2));
        const float mn0 = fmaxf(m0, mx0), mn1 = fmaxf(m1, mx1);
        const float c0 = __expf(m0 - mn0), c1 = __expf(m1 - mn1);
        float s0 = 0.f, s1 = 0.f;
#pragma unroll
        for (int j = 0; j < 8; j++) {
            S[j][0] = __expf(S[j][0] - mn0);
            S[j][1] = __expf(S[j][1] - mn0);
            S[j][2] = __expf(S[j][2] - mn1);
            S[j][3] = __expf(S[j][3] - mn1);
            s0 += S[j][0] + S[j][1];
            s1 += S[j][2] + S[j][3];
        }
        s0 += __shfl_xor_sync(0xffffffffu, s0, 1);
        s0 += __shfl_xor_sync(0xffffffffu, s0, 2);
        s1 += __shfl_xor_sync(0xffffffffu, s1, 1);
        s1 += __shfl_xor_sync(0xffffffffu, s1, 2);
        l0 = l0 * c0 + s0;
        l1 = l1 * c1 + s1;
        m0 = mn0; m1 = mn1;
#pragma unroll
        for (int i = 0; i < 16; i++) {
            o[i][0] *= c0; o[i][1] *= c0;
            o[i][2] *= c1; o[i][3] *= c1;
        }

        uint32_t ap[4][4];
#pragma unroll
        for (int i = 0; i < 4; i++) {
            __half2 h0 = __floats2half2_rn(S[2 * i][0], S[2 * i][1]);
            __half2 h1 = __floats2half2_rn(S[2 * i][2], S[2 * i][3]);
            __half2 h2 = __floats2half2_rn(S[2 * i + 1][0], S[2 * i + 1][1]);
            __half2 h3 = __floats2half2_rn(S[2 * i + 1][2], S[2 * i + 1][3]);
            ap[i][0] = *(uint32_t*)&h0;
            ap[i][1] = *(uint32_t*)&h1;
            ap[i][2] = *(uint32_t*)&h2;
            ap[i][3] = *(uint32_t*)&h3;
        }

#pragma unroll
        for (int i = 0; i < 4; i++) {
            const uint32_t vx = (uint32_t)(((i * 2 + segb) ^ b_swrow) << 4);
#pragma unroll
            for (int nt = 0; nt < 8; nt++) {
                uint32_t b[4];
                ldsm_x4(b, vbuf + (uint32_t)((nt * 16 + rb) * 128) + vx);
                mma16816(o[nt * 2],     ap[i], b[0], b[1]);
                mma16816(o[nt * 2 + 1], ap[i], b[2], b[3]);
            }
        }

        __syncthreads();
        if (kb + 2 < kend) load_kv(kb + 2, kb & 1);
        else asm volatile("cp.async.commit_group;");
        asm volatile("cp.async.wait_group 1;");
        __syncthreads();
    }

    const float inv0 = 1.f / l0, inv1 = 1.f / l1;
    const int r0 = qb * 128 + w * 16 + g;
#pragma unroll
    for (int nt = 0; nt < 16; nt++) {
        const int col = h * DV + nt * 8 + t4 * 2;
        __half2 lo = __floats2half2_rn(o[nt][0] * inv0, o[nt][1] * inv0);
        __half2 hi = __floats2half2_rn(o[nt][2] * inv1, o[nt][3] * inv1);
        *(__half2*)&O[(size_t)r0 * HDIM + col] = lo;
        *(__half2*)&O[(size_t)(r0 + 8) * HDIM + col] = hi;
    }
}

// ---------------- fp32 -> fp16 convert (MLP=2: two independent float4 loads) ----------------
__global__ __launch_bounds__(256) void cvt_act4(
    const float4* __restrict__ X, uint2* __restrict__ X2, int total4)
{
    const int half = total4 >> 1;
    int i = blockIdx.x * 256 + threadIdx.x;
    if (i >= half) return;
    float4 v0 = X[i];
    float4 v1 = X[i + half];
    __half2 a0 = __floats2half2_rn(v0.x, v0.y);
    __half2 b0 = __floats2half2_rn(v0.z, v0.w);
    __half2 a1 = __floats2half2_rn(v1.x, v1.y);
    __half2 b1 = __floats2half2_rn(v1.z, v1.w);
    uint2 o0, o1;
    o0.x = *(uint32_t*)&a0; o0.y = *(uint32_t*)&b0;
    o1.x = *(uint32_t*)&a1; o1.y = *(uint32_t*)&b1;
    X2[i] = o0;
    X2[i + half] = o1;
}

// ---------------- weight transpose+convert: 64k x 32n tiles, 8 elem/thread ----------------
__global__ __launch_bounds__(256) void transpose_w_h(
    const float* __restrict__ W, __half* __restrict__ Wt, int K, int N)
{
    __shared__ __half tt[32][72];   // [n][k], 144B rows (16B-aligned vector reads)
    const int kb = blockIdx.x * 64, nb = blockIdx.y * 32;
    const int tx = threadIdx.x & 7, ty = threadIdx.x >> 3;   // ty 0..31
    float4 v0 = *(const float4*)&W[(size_t)(kb + ty) * N + nb + tx * 4];
    float4 v1 = *(const float4*)&W[(size_t)(kb + 32 + ty) * N + nb + tx * 4];
    tt[tx * 4 + 0][ty] = __float2half_rn(v0.x);
    tt[tx * 4 + 1][ty] = __float2half_rn(v0.y);
    tt[tx * 4 + 2][ty] = __float2half_rn(v0.z);
    tt[tx * 4 + 3][ty] = __float2half_rn(v0.w);
    tt[tx * 4 + 0][32 + ty] = __float2half_rn(v1.x);
    tt[tx * 4 + 1][32 + ty] = __float2half_rn(v1.y);
    tt[tx * 4 + 2][32 + ty] = __float2half_rn(v1.z);
    tt[tx * 4 + 3][32 + ty] = __float2half_rn(v1.w);
    __syncthreads();
    *(uint4*)&Wt[(size_t)(nb + ty) * K + kb + tx * 8] = *(const uint4*)&tt[ty][tx * 8];
}

// ---------------- RoPE trig table ----------------
__global__ __launch_bounds__(256) void rope_table(float2* __restrict__ trig)
{
    int idx = blockIdx.x * 256 + threadIdx.x;
    if (idx >= SEQ * 32) return;
    int s = idx >> 5, i = idx & 31;
    float inv_freq = powf(10000.f, -(float)(2 * i) / 64.f);
    float sn, cs;
    sincosf((float)s * inv_freq, &sn, &cs);
    trig[idx] = make_float2(cs, sn);
}

// ---------------- V pack: kvp[s][h*256+128+d] -> V2[h][d][s], coalesced ----------------
__global__ __launch_bounds__(256) void v_pack(
    const __half* __restrict__ kvp, __half* __restrict__ V2)
{
    __shared__ __half tt[32][40];
    const int s0 = blockIdx.x * 32;
    const int d0 = blockIdx.y * 32;
    const int h  = blockIdx.z;
    const int tx = threadIdx.x & 7, ty = threadIdx.x >> 3;
    uint2 v = *(const uint2*)&kvp[(size_t)(s0 + ty) * KVB_N + h * (DN + DV) + DN + d0 + tx * 4];
    __half2 a = *(__half2*)&v.x, b = *(__half2*)&v.y;
    tt[tx * 4 + 0][ty] = a.x;
    tt[tx * 4 + 1][ty] = a.y;
    tt[tx * 4 + 2][ty] = b.x;
    tt[tx * 4 + 3][ty] = b.y;
    __syncthreads();
    __half2 c, d;
    c.x = tt[ty][tx * 4 + 0]; c.y = tt[ty][tx * 4 + 1];
    d.x = tt[ty][tx * 4 + 2]; d.y = tt[ty][tx * 4 + 3];
    uint2 o;
    o.x = *(uint32_t*)&c;
    o.y = *(uint32_t*)&d;
    *(uint2*)&V2[((size_t)h * DV + d0 + ty) * SEQ + s0 + tx * 4] = o;
}

// ---------------- RMSNorm -> fp16 (float4 loads, 4-half stores) ----------------
__global__ __launch_bounds__(256) void rmsnorm_h(
    const float* __restrict__ src, const float* __restrict__ gamma,
    __half* __restrict__ dst, int stride, int len)
{
    const int row = blockIdx.x;
    const float* x = src + (size_t)row * stride;
    const int len4 = len >> 2;
    float ss = 0.f;
    for (int i = threadIdx.x; i < len4; i += 256) {
        float4 v = ((const float4*)x)[i];
        ss += v.x * v.x + v.y * v.y + v.z * v.z + v.w * v.w;
    }
#pragma unroll
    for (int o = 16; o; o >>= 1) ss += __shfl_xor_sync(0xffffffffu, ss, o);
    __shared__ float ws[8]; __shared__ float s_inv;
    if ((threadIdx.x & 31) == 0) ws[threadIdx.x >> 5] = ss;
    __syncthreads();
    if (threadIdx.x == 0) {
        float t = 0.f;
#pragma unroll
        for (int i = 0; i < 8; i++) t += ws[i];
        s_inv = rsqrtf(t / (float)len + 1e-6f);
    }
    __syncthreads();
    const float inv = s_inv;
    __half* out = dst + (size_t)row * len;
    for (int i = threadIdx.x; i < len4; i += 256) {
        float4 v = ((const float4*)x)[i];
        float4 gm = ((const float4*)gamma)[i];
        __half2 a = __floats2half2_rn(v.x * gm.x * inv, v.y * gm.y * inv);
        __half2 b = __floats2half2_rn(v.z * gm.z * inv, v.w * gm.w * inv);
        uint2 o;
        o.x = *(uint32_t*)&a;
        o.y = *(uint32_t*)&b;
        *(uint2*)&out[i * 4] = o;
    }
}

// ---------------- RoPE + pack Q/K: one block per s, loop over heads ----------------
__global__ __launch_bounds__(192) void rope_qk(
    const __half* __restrict__ qp, const __half* __restrict__ kvp,
    const float* __restrict__ fused, const float2* __restrict__ trig,
    __half* __restrict__ Q2, __half* __restrict__ K2)
{
    const int s = blockIdx.x, d = threadIdx.x;
    const float scale = 0.07216878364870323f; // 1/sqrt(192)
    float cs = 0.f, sn = 0.f, kv_pe = 0.f;
    if (d >= DN) {
        int j = d - DN, i = j & 31;
        float2 t = trig[s * 32 + i];
        cs = t.x; sn = t.y;
        size_t koff = (size_t)s * FUSED_NPAD + (QL + KL);
        float kpe = fused[koff + j];
        float krot = (j < 32) ? -fused[koff + j + 32] : fused[koff + j - 32];
        kv_pe = kpe * cs + krot * sn;          // k_pe shared across all heads
    }
#pragma unroll 4
    for (int h = 0; h < NH; h++) {
        float qv, kv;
        if (d < DN) {
            qv = __half2float(qp[(size_t)s * QB_N + h * DFULL + d]) * scale;
            kv = __half2float(kvp[(size_t)s * KVB_N + h * (DN + DV) + d]);
        } else {
            int j = d - DN;
            size_t qoff = (size_t)s * QB_N + h * DFULL + DN;
            float qpe = __half2float(qp[qoff + j]);
            float qrot = (j < 32) ? -__half2float(qp[qoff + j + 32])
                                  :  __half2float(qp[qoff + j - 32]);
            qv = (qpe * cs + qrot * sn) * scale;
            kv = kv_pe;
        }
        Q2[((size_t)h * SEQ + s) * DFULL + d] = __float2half_rn(qv);
        K2[((size_t)h * SEQ + s) * DFULL + d] = __float2half_rn(kv);
    }
}

// ---------------- launcher (multi-stream fork/join, capture-legal) ----------------
extern "C" void kernel_launch(void* const* d_in, const int* in_sizes, int n_in,
                              void* d_out, int out_size)
{
    const float* hidden     = (const float*)d_in[0];
    const float* w_kv_a     = (const float*)d_in[1];
    const float* q_a_gamma  = (const float*)d_in[2];
    const float* w_qb       = (const float*)d_in[3];
    const float* kv_a_gamma = (const float*)d_in[4];
    const float* w_kvb      = (const float*)d_in[5];
    const float* w_o        = (const float*)d_in[6];
    float* out = (float*)d_out;

    static float* fused = nullptr;
    static float2* trig;
    static __half *qp, *kvp, *H2, *QN2, *KVN2, *ATTN2, *WKVA2, *WQB2, *WKVB2, *WO2, *Q2, *K2, *V2;
    static cudaStream_t sB, sC;
    static cudaEvent_t evRoot, evWA, evB, evG1, evC;
    if (!fused) {
        cudaGetSymbolAddress((void**)&fused, g_fused);
        cudaGetSymbolAddress((void**)&qp,    g_qp);
        cudaGetSymbolAddress((void**)&kvp,   g_kvp);
        cudaGetSymbolAddress((void**)&trig,  g_trig);
        cudaGetSymbolAddress((void**)&H2,    g_H2);
        cudaGetSymbolAddress((void**)&QN2,   g_QN2);
        cudaGetSymbolAddress((void**)&KVN2,  g_KVN2);
        cudaGetSymbolAddress((void**)&ATTN2, g_ATTN2);
        cudaGetSymbolAddress((void**)&WKVA2, g_WKVA2);
        cudaGetSymbolAddress((void**)&WQB2,  g_WQB2);
        cudaGetSymbolAddress((void**)&WKVB2, g_WKVB2);
        cudaGetSymbolAddress((void**)&WO2,   g_WO2);
        cudaGetSymbolAddress((void**)&Q2,    g_Q2);
        cudaGetSymbolAddress((void**)&K2,    g_K2);
        cudaGetSymbolAddress((void**)&V2,    g_V2);
        cudaFuncSetAttribute(gemm_fp16, cudaFuncAttributeMaxDynamicSharedMemorySize, GSMEM);
        cudaFuncSetAttribute(flash_mma, cudaFuncAttributeMaxDynamicSharedMemorySize, FSMEM);
        cudaStreamCreateWithFlags(&sB, cudaStreamNonBlocking);
        cudaStreamCreateWithFlags(&sC, cudaStreamNonBlocking);
        cudaEventCreateWithFlags(&evRoot, cudaEventDisableTiming);
        cudaEventCreateWithFlags(&evWA,   cudaEventDisableTiming);
        cudaEventCreateWithFlags(&evB,    cudaEventDisableTiming);
        cudaEventCreateWithFlags(&evG1,   cudaEventDisableTiming);
        cudaEventCreateWithFlags(&evC,    cudaEventDisableTiming);
    }

    // ---- fork: stream B — WKVA transpose FIRST (GEMM1 gate), then the rest ----
    cudaEventRecord(evRoot, 0);
    cudaStreamWaitEvent(sB, evRoot, 0);
    transpose_w_h<<<dim3(HDIM / 64, FUSED_REAL / 32), 256, 0, sB>>>(w_kv_a, WKVA2, HDIM, FUSED_REAL);
    cudaEventRecord(evWA, sB);
    transpose_w_h<<<dim3(QL / 64, QB_N / 32), 256, 0, sB>>>(w_qb, WQB2, QL, QB_N);
    transpose_w_h<<<dim3(KL / 64, KVB_N / 32), 256, 0, sB>>>(w_kvb, WKVB2, KL, KVB_N);
    transpose_w_h<<<dim3(HDIM / 64, HDIM / 32), 256, 0, sB>>>(w_o, WO2, HDIM, HDIM);
    rope_table<<<(SEQ * 32 + 255) / 256, 256, 0, sB>>>(trig);
    cudaEventRecord(evB, sB);

    // ---- main stream: cvt runs concurrently with WKVA transpose ----
    cvt_act4<<<(SEQ * HDIM / 8 + 255) / 256, 256>>>(
        (const float4*)hidden, (uint2*)H2, SEQ * HDIM / 4);
    cudaStreamWaitEvent(0, evWA, 0);
    gemm_fp16<<<dim3(FUSED_NPAD / 128, SEQ / 128), 256, GSMEM>>>(
        H2, WKVA2, fused, HDIM, HDIM, FUSED_NPAD, HDIM, 0);
    cudaEventRecord(evG1, 0);

    // ---- stream C: KV branch (rmsnorm_kv -> GEMM3 -> v_pack, fp16) ----
    cudaStreamWaitEvent(sC, evG1, 0);
    cudaStreamWaitEvent(sC, evB, 0);
    rmsnorm_h<<<SEQ, 256, 0, sC>>>(fused + QL, kv_a_gamma, KVN2, FUSED_NPAD, KL);
    gemm_fp16<<<dim3(KVB_N / 128, SEQ / 128), 256, GSMEM, sC>>>(
        KVN2, WKVB2, (float*)kvp, KL, KL, KVB_N, KL, 1);
    v_pack<<<dim3(SEQ / 32, DV / 32, NH), 256, 0, sC>>>(kvp, V2);
    cudaEventRecord(evC, sC);

    // ---- main stream: Q branch (fp16 out) ----
    rmsnorm_h<<<SEQ, 256>>>(fused, q_a_gamma, QN2, FUSED_NPAD, QL);
    cudaStreamWaitEvent(0, evB, 0);
    gemm_fp16<<<dim3(QB_N / 128, SEQ / 128), 256, GSMEM>>>(
        QN2, WQB2, (float*)qp, QL, QL, QB_N, QL, 1);

    // ---- join: rope needs qp (main) + kvp (stream C) + trig (evB) ----
    cudaStreamWaitEvent(0, evC, 0);
    rope_qk<<<SEQ, 192>>>(qp, kvp, fused, trig, Q2, K2);

    // fused causal flash attention -> fp16 ATTN2
    flash_mma<<<dim3(SEQ / 128, NH), 256, FSMEM>>>(Q2, K2, V2, ATTN2);

    // out = attn @ w_o
    gemm_fp16<<<dim3(HDIM / 128, SEQ / 128), 256, GSMEM>>>(
        ATTN2, WO2, out, HDIM, HDIM, HDIM, HDIM, 0);
}